// round 6
// baseline (speedup 1.0000x reference)
#include <cuda_runtime.h>
#include <cuda_bf16.h>
#include <cstdint>

#define HID 1024
#define NEG_SLOPE 0.2f

static const int NMAX = 10240;
static const int EMAX = 163840;
#define TMAX (EMAX + NMAX)

// ---------------- scratch (static device globals) ----------------
__device__ __align__(16) float g_xl[(size_t)NMAX * HID];
__device__ __align__(16) float g_xr[(size_t)NMAX * HID];
__device__ int   g_deg[NMAX];
__device__ int   g_cur[NMAX];
__device__ int   g_off[NMAX + 1];
__device__ int   g_csr[TMAX];

// bf16 hi/lo split activations
__device__ __align__(16) __nv_bfloat16 g_xh [(size_t)NMAX * 512];
__device__ __align__(16) __nv_bfloat16 g_xlo[(size_t)NMAX * 512];
__device__ __align__(16) __nv_bfloat16 g_hh [(size_t)NMAX * HID];
__device__ __align__(16) __nv_bfloat16 g_hl [(size_t)NMAX * HID];
__device__ __align__(16) __nv_bfloat16 g_h1h[(size_t)NMAX * 512];
__device__ __align__(16) __nv_bfloat16 g_h1l[(size_t)NMAX * 512];
__device__ __align__(16) __nv_bfloat16 g_h2h[(size_t)NMAX * 128];
__device__ __align__(16) __nv_bfloat16 g_h2l[(size_t)NMAX * 128];

// transposed + split weights: Wt[n][k]
__device__ __align__(16) __nv_bfloat16 g_Wlt_h[1024 * 512], g_Wlt_l[1024 * 512];
__device__ __align__(16) __nv_bfloat16 g_Wrt_h[1024 * 512], g_Wrt_l[1024 * 512];
__device__ __align__(16) __nv_bfloat16 g_W1t_h[512 * 1024], g_W1t_l[512 * 1024];
__device__ __align__(16) __nv_bfloat16 g_W2t_h[128 * 512],  g_W2t_l[128 * 512];
__device__ __align__(16) __nv_bfloat16 g_Wct_h[112 * 128],  g_Wct_l[112 * 128];

// ---------------- PTX helpers (plain compute_103 ISA only) ----------------
__device__ __forceinline__ uint32_t smem_u32(const void* p) {
    uint32_t a;
    asm("{ .reg .u64 t; cvta.to.shared.u64 t, %1; cvt.u32.u64 %0, t; }"
        : "=r"(a) : "l"(p));
    return a;
}
__device__ __forceinline__ void cp16(uint32_t saddr, const void* gaddr, int srcsize) {
    asm volatile("cp.async.cg.shared.global [%0], [%1], 16, %2;"
                 :: "r"(saddr), "l"(gaddr), "r"(srcsize) : "memory");
}
#define CP_COMMIT() asm volatile("cp.async.commit_group;" ::: "memory")
#define CP_WAIT(n)  asm volatile("cp.async.wait_group %0;" :: "n"(n) : "memory")

__device__ __forceinline__ void ldsm4(uint32_t& r0, uint32_t& r1, uint32_t& r2,
                                      uint32_t& r3, uint32_t a) {
    asm volatile("ldmatrix.sync.aligned.m8n8.x4.shared.b16 {%0,%1,%2,%3}, [%4];"
                 : "=r"(r0), "=r"(r1), "=r"(r2), "=r"(r3) : "r"(a));
}
__device__ __forceinline__ void mma16816(float* d, const uint32_t* a,
                                         uint32_t b0, uint32_t b1) {
    asm volatile(
        "mma.sync.aligned.m16n8k16.row.col.f32.bf16.bf16.f32 "
        "{%0,%1,%2,%3}, {%4,%5,%6,%7}, {%8,%9}, {%0,%1,%2,%3};"
        : "+f"(d[0]), "+f"(d[1]), "+f"(d[2]), "+f"(d[3])
        : "r"(a[0]), "r"(a[1]), "r"(a[2]), "r"(a[3]), "r"(b0), "r"(b1));
}

// ============================================================================
// bf16-split GEMM on mma.sync (identical to round-4 winner)
// ============================================================================
#define TILE_B   8192
#define STAGE_B  (4 * TILE_B)
#define GSMEM    (2 * STAGE_B)

__device__ __forceinline__ void fill_tile_async(
    uint32_t dst, const __nv_bfloat16* __restrict__ src,
    int rowbase, int limit, int K, int k0, int tid)
{
    int fr = tid >> 2;
    int fc = tid & 3;
#pragma unroll
    for (int it = 0; it < 2; it++) {
        int row = fr + it * 64;
        int grow = rowbase + row;
        uint32_t saddr = dst + row * 64 + ((fc ^ ((row >> 1) & 3)) * 16);
        const void* g = src + (size_t)grow * K + k0 + fc * 8;
        cp16(saddr, g, (grow < limit) ? 16 : 0);
    }
}

template <bool RELU, bool WF32, bool WBF16>
__global__ __launch_bounds__(256, 1)
void gemm_mma(const __nv_bfloat16* __restrict__ Ah, const __nv_bfloat16* __restrict__ Al,
              const __nv_bfloat16* __restrict__ Bh, const __nv_bfloat16* __restrict__ Bl,
              const float* __restrict__ bias,
              float* __restrict__ C, __nv_bfloat16* __restrict__ Ch,
              __nv_bfloat16* __restrict__ Cl,
              int M, int Nn, int K)
{
    extern __shared__ char smem[];
    const uint32_t sb = smem_u32(smem);
    const int tid = threadIdx.x;
    const int wid = tid >> 5;
    const int lane = tid & 31;
    const int row0 = blockIdx.y * 128;
    const int col0 = blockIdx.x * 128;
    const int wm0 = (wid & 3) * 32;
    const int wn0 = (wid >> 2) * 64;

    float acc[2][8][4];
#pragma unroll
    for (int i = 0; i < 2; i++)
#pragma unroll
        for (int j = 0; j < 8; j++)
#pragma unroll
            for (int k = 0; k < 4; k++) acc[i][j][k] = 0.f;

    uint32_t aoff[2][2], boff[4][2];
#pragma unroll
    for (int mt = 0; mt < 2; mt++) {
        int arow = wm0 + mt * 16 + (lane & 15);
        int hi = lane >> 4;
#pragma unroll
        for (int s = 0; s < 2; s++) {
            int chunk = s * 2 + hi;
            aoff[mt][s] = arow * 64 + ((chunk ^ ((arow >> 1) & 3)) * 16);
        }
    }
#pragma unroll
    for (int bt = 0; bt < 4; bt++) {
        int brow = wn0 + bt * 16 + (lane & 7) + ((lane >> 4) & 1) * 8;
        int hi = (lane >> 3) & 1;
#pragma unroll
        for (int s = 0; s < 2; s++) {
            int chunk = s * 2 + hi;
            boff[bt][s] = brow * 64 + ((chunk ^ ((brow >> 1) & 3)) * 16);
        }
    }

    const int nC = K / 32;

    {
        uint32_t st = sb;
        fill_tile_async(st + 0 * TILE_B, Ah, row0, M,  K, 0, tid);
        fill_tile_async(st + 1 * TILE_B, Al, row0, M,  K, 0, tid);
        fill_tile_async(st + 2 * TILE_B, Bh, col0, Nn, K, 0, tid);
        fill_tile_async(st + 3 * TILE_B, Bl, col0, Nn, K, 0, tid);
        CP_COMMIT();
    }

    for (int c = 0; c < nC; c++) {
        const uint32_t st = sb + (c & 1) * STAGE_B;
        if (c + 1 < nC) {
            uint32_t nx = sb + ((c + 1) & 1) * STAGE_B;
            int k0 = (c + 1) * 32;
            fill_tile_async(nx + 0 * TILE_B, Ah, row0, M,  K, k0, tid);
            fill_tile_async(nx + 1 * TILE_B, Al, row0, M,  K, k0, tid);
            fill_tile_async(nx + 2 * TILE_B, Bh, col0, Nn, K, k0, tid);
            fill_tile_async(nx + 3 * TILE_B, Bl, col0, Nn, K, k0, tid);
            CP_COMMIT();
            CP_WAIT(1);
        } else {
            CP_WAIT(0);
        }
        __syncthreads();

#pragma unroll
        for (int s = 0; s < 2; s++) {
            uint32_t ah[2][4], al[2][4], bh[4][4], bl[4][4];
#pragma unroll
            for (int mt = 0; mt < 2; mt++) {
                ldsm4(ah[mt][0], ah[mt][1], ah[mt][2], ah[mt][3],
                      st + 0 * TILE_B + aoff[mt][s]);
                ldsm4(al[mt][0], al[mt][1], al[mt][2], al[mt][3],
                      st + 1 * TILE_B + aoff[mt][s]);
            }
#pragma unroll
            for (int bt = 0; bt < 4; bt++) {
                ldsm4(bh[bt][0], bh[bt][1], bh[bt][2], bh[bt][3],
                      st + 2 * TILE_B + boff[bt][s]);
                ldsm4(bl[bt][0], bl[bt][1], bl[bt][2], bl[bt][3],
                      st + 3 * TILE_B + boff[bt][s]);
            }
#pragma unroll
            for (int mt = 0; mt < 2; mt++) {
#pragma unroll
                for (int bt = 0; bt < 4; bt++) {
                    mma16816(acc[mt][2 * bt + 0], ah[mt], bh[bt][0], bh[bt][1]);
                    mma16816(acc[mt][2 * bt + 1], ah[mt], bh[bt][2], bh[bt][3]);
                    mma16816(acc[mt][2 * bt + 0], ah[mt], bl[bt][0], bl[bt][1]);
                    mma16816(acc[mt][2 * bt + 1], ah[mt], bl[bt][2], bl[bt][3]);
                    mma16816(acc[mt][2 * bt + 0], al[mt], bh[bt][0], bh[bt][1]);
                    mma16816(acc[mt][2 * bt + 1], al[mt], bh[bt][2], bh[bt][3]);
                }
            }
        }
        __syncthreads();
    }

#pragma unroll
    for (int mt = 0; mt < 2; mt++) {
#pragma unroll
        for (int nt = 0; nt < 8; nt++) {
            int col = col0 + wn0 + nt * 8 + (lane & 3) * 2;
            if (col >= Nn) continue;
            float bx = bias[col], by = bias[col + 1];
#pragma unroll
            for (int half = 0; half < 2; half++) {
                int grow = row0 + wm0 + mt * 16 + (lane >> 2) + half * 8;
                if (grow >= M) continue;
                float ox = acc[mt][nt][half * 2 + 0] + bx;
                float oy = acc[mt][nt][half * 2 + 1] + by;
                if (RELU) { ox = fmaxf(ox, 0.f); oy = fmaxf(oy, 0.f); }
                size_t idx = (size_t)grow * Nn + col;
                if (WF32) {
                    *(float2*)(C + idx) = make_float2(ox, oy);
                }
                if (WBF16) {
                    __nv_bfloat16 hx = __float2bfloat16(ox);
                    __nv_bfloat16 hy = __float2bfloat16(oy);
                    *(__nv_bfloat162*)(Ch + idx) = __nv_bfloat162(hx, hy);
                    *(__nv_bfloat162*)(Cl + idx) = __floats2bfloat162_rn(
                        ox - __bfloat162float(hx), oy - __bfloat162float(hy));
                }
            }
        }
    }
}

// ============================================================================
// Conversions
// ============================================================================
__global__ void split_x_kernel(const float4* __restrict__ src,
                               __nv_bfloat162* __restrict__ h2,
                               __nv_bfloat162* __restrict__ l2, int n4)
{
    int i = blockIdx.x * blockDim.x + threadIdx.x;
    if (i >= n4) return;
    float4 v = src[i];
    __nv_bfloat16 hx = __float2bfloat16(v.x), hy = __float2bfloat16(v.y);
    __nv_bfloat16 hz = __float2bfloat16(v.z), hw = __float2bfloat16(v.w);
    h2[i * 2 + 0] = __floats2bfloat162_rn(v.x, v.y);
    h2[i * 2 + 1] = __floats2bfloat162_rn(v.z, v.w);
    l2[i * 2 + 0] = __floats2bfloat162_rn(v.x - __bfloat162float(hx), v.y - __bfloat162float(hy));
    l2[i * 2 + 1] = __floats2bfloat162_rn(v.z - __bfloat162float(hz), v.w - __bfloat162float(hw));
}

__global__ void tsplit_kernel(const float* __restrict__ W,
                              __nv_bfloat16* __restrict__ th, __nv_bfloat16* __restrict__ tl,
                              int K, int N)
{
    __shared__ float t[32][33];
    int k0 = blockIdx.y * 32, n0 = blockIdx.x * 32;
    int tx = threadIdx.x, ty = threadIdx.y;
#pragma unroll
    for (int i = 0; i < 4; i++) {
        int k = k0 + ty + i * 8;
        t[ty + i * 8][tx] = (k < K && n0 + tx < N) ? W[(size_t)k * N + n0 + tx] : 0.f;
    }
    __syncthreads();
#pragma unroll
    for (int i = 0; i < 4; i++) {
        int n = n0 + ty + i * 8;
        int k = k0 + tx;
        if (n < N && k < K) {
            float v = t[tx][ty + i * 8];
            __nv_bfloat16 hb = __float2bfloat16(v);
            th[(size_t)n * K + k] = hb;
            tl[(size_t)n * K + k] = __float2bfloat16(v - __bfloat162float(hb));
        }
    }
}

// ============================================================================
// CSR build
// ============================================================================
__global__ void init_kernel(int n) {
    int i = blockIdx.x * blockDim.x + threadIdx.x;
    if (i < n) { g_deg[i] = 1; g_cur[i] = 0; }
}
__global__ void count_kernel(const int* __restrict__ dst, int E) {
    int k = blockIdx.x * blockDim.x + threadIdx.x;
    if (k < E) atomicAdd(&g_deg[dst[k]], 1);
}
__global__ __launch_bounds__(1024)
void scan_kernel(int n) {
    __shared__ int part[1024];
    int tid = threadIdx.x;
    int chunk = (n + 1023) >> 10;
    int beg = tid * chunk;
    int end = min(beg + chunk, n);
    int s = 0;
    for (int i = beg; i < end; i++) s += g_deg[i];
    part[tid] = s;
    __syncthreads();
    for (int d = 1; d < 1024; d <<= 1) {
        int v = part[tid];
        int a = (tid >= d) ? part[tid - d] : 0;
        __syncthreads();
        part[tid] = v + a;
        __syncthreads();
    }
    int run = (tid > 0) ? part[tid - 1] : 0;
    for (int i = beg; i < end; i++) { g_off[i] = run; run += g_deg[i]; }
    if (tid == 1023) g_off[n] = part[1023];
}
__global__ void fill_kernel(const int* __restrict__ dst, int E, int total) {
    int k = blockIdx.x * blockDim.x + threadIdx.x;
    if (k >= total) return;
    int d = (k < E) ? dst[k] : (k - E);
    int pos = atomicAdd(&g_cur[d], 1);
    g_csr[g_off[d] + pos] = k;
}

// ============================================================================
// FUSED edge-score + segment-softmax + aggregation.  Block per dst node.
// xr[node] and att cached in SMEM (per-node, not per-edge).  Online softmax
// over degree chunks -> correct for any degree.  Writes bf16 hi/lo of relu(h).
// ============================================================================
#define CHUNK 1024
__global__ __launch_bounds__(256)
void agg_fused_kernel(const int* __restrict__ src,
                      const float* __restrict__ att,
                      const float* __restrict__ conv_b, int E)
{
    const int node = blockIdx.x;
    const int tid = threadIdx.x;
    const int wid = tid >> 5;
    const int lane = tid & 31;
    const int beg = g_off[node];
    const int deg = g_off[node + 1] - beg;

    __shared__ __align__(16) float s_xr[HID];
    __shared__ __align__(16) float s_att[HID];
    __shared__ float s_w[CHUNK];
    __shared__ int   s_src[CHUNK];
    __shared__ float red[8];

    // cache xr[node] and att
    {
        const float4* xr4 = (const float4*)(g_xr + (size_t)node * HID);
        const float4* at4 = (const float4*)att;
        ((float4*)s_xr)[tid] = xr4[tid];
        ((float4*)s_att)[tid] = at4[tid];
    }
    __syncthreads();

    float m = -1e30f, ssum = 0.f;
    float4 acc = make_float4(0.f, 0.f, 0.f, 0.f);

    for (int c0 = 0; c0 < deg; c0 += CHUNK) {
        const int clen = min(CHUNK, deg - c0);

        // ---- pass 1: warp-per-edge scores ----
        for (int j = wid; j < clen; j += 8) {
            int k = g_csr[beg + c0 + j];
            int sidx = (k < E) ? src[k] : (k - E);
            if (lane == 0) s_src[j] = sidx;
            const float4* xl4 = (const float4*)(g_xl + (size_t)sidx * HID);
            const float4* xr4 = (const float4*)s_xr;
            const float4* at4 = (const float4*)s_att;
            float e = 0.f;
#pragma unroll
            for (int t = 0; t < 8; t++) {
                int idx = lane + t * 32;
                float4 a = xl4[idx];
                float4 b = xr4[idx];
                float4 w = at4[idx];
                float v;
                v = a.x + b.x; v = (v > 0.f) ? v : NEG_SLOPE * v; e = fmaf(v, w.x, e);
                v = a.y + b.y; v = (v > 0.f) ? v : NEG_SLOPE * v; e = fmaf(v, w.y, e);
                v = a.z + b.z; v = (v > 0.f) ? v : NEG_SLOPE * v; e = fmaf(v, w.z, e);
                v = a.w + b.w; v = (v > 0.f) ? v : NEG_SLOPE * v; e = fmaf(v, w.w, e);
            }
#pragma unroll
            for (int o = 16; o > 0; o >>= 1) e += __shfl_xor_sync(0xffffffffu, e, o);
            if (lane == 0) s_w[j] = e;
        }
        __syncthreads();

        // ---- chunk max (block reduce) ----
        float cm = -1e30f;
        for (int j = tid; j < clen; j += 256) cm = fmaxf(cm, s_w[j]);
#pragma unroll
        for (int o = 16; o > 0; o >>= 1) cm = fmaxf(cm, __shfl_xor_sync(0xffffffffu, cm, o));
        if (lane == 0) red[wid] = cm;
        __syncthreads();
        cm = red[0];
#pragma unroll
        for (int w = 1; w < 8; w++) cm = fmaxf(cm, red[w]);

        // ---- online rescale ----
        float nm = fmaxf(m, cm);
        float r = __expf(m - nm);      // m=-inf first time -> 0, acc/ssum are 0
        ssum *= r;
        acc.x *= r; acc.y *= r; acc.z *= r; acc.w *= r;
        m = nm;
        __syncthreads();

        // exp in place + chunk sum
        float sl = 0.f;
        for (int j = tid; j < clen; j += 256) {
            float w = __expf(s_w[j] - nm);
            s_w[j] = w;
            sl += w;
        }
#pragma unroll
        for (int o = 16; o > 0; o >>= 1) sl += __shfl_xor_sync(0xffffffffu, sl, o);
        if (lane == 0) red[wid] = sl;
        __syncthreads();
        {
            float t = red[0];
#pragma unroll
            for (int w = 1; w < 8; w++) t += red[w];
            ssum += t;
        }

        // ---- pass 2: weighted sum, thread-per-float4 ----
        for (int j = 0; j < clen; j++) {
            float wgt = s_w[j];
            const float4* row = (const float4*)(g_xl + (size_t)s_src[j] * HID);
            float4 v = row[tid];
            acc.x = fmaf(wgt, v.x, acc.x);
            acc.y = fmaf(wgt, v.y, acc.y);
            acc.z = fmaf(wgt, v.z, acc.z);
            acc.w = fmaf(wgt, v.w, acc.w);
        }
        __syncthreads();
    }

    float inv = 1.f / ssum;
    float4 cb = ((const float4*)conv_b)[tid];
    float4 o;
    o.x = fmaxf(fmaf(acc.x, inv, cb.x), 0.f);
    o.y = fmaxf(fmaf(acc.y, inv, cb.y), 0.f);
    o.z = fmaxf(fmaf(acc.z, inv, cb.z), 0.f);
    o.w = fmaxf(fmaf(acc.w, inv, cb.w), 0.f);

    size_t base = (size_t)node * HID + tid * 4;
    __nv_bfloat16 hx = __float2bfloat16(o.x), hy = __float2bfloat16(o.y);
    __nv_bfloat16 hz = __float2bfloat16(o.z), hw = __float2bfloat16(o.w);
    __nv_bfloat162* hh2 = (__nv_bfloat162*)(g_hh + base);
    __nv_bfloat162* hl2 = (__nv_bfloat162*)(g_hl + base);
    hh2[0] = __floats2bfloat162_rn(o.x, o.y);
    hh2[1] = __floats2bfloat162_rn(o.z, o.w);
    hl2[0] = __floats2bfloat162_rn(o.x - __bfloat162float(hx), o.y - __bfloat162float(hy));
    hl2[1] = __floats2bfloat162_rn(o.z - __bfloat162float(hz), o.w - __bfloat162float(hw));
}

// ============================================================================
// launch
// ============================================================================
extern "C" void kernel_launch(void* const* d_in, const int* in_sizes, int n_in,
                              void* d_out, int out_size)
{
    const float* x   = (const float*)d_in[0];
    const int*   ei  = (const int*)d_in[1];
    const float* Wl  = (const float*)d_in[2];
    const float* bl  = (const float*)d_in[3];
    const float* Wr  = (const float*)d_in[4];
    const float* br  = (const float*)d_in[5];
    const float* att = (const float*)d_in[6];
    const float* cb  = (const float*)d_in[7];
    const float* W1  = (const float*)d_in[8];
    const float* b1  = (const float*)d_in[9];
    const float* W2  = (const float*)d_in[10];
    const float* b2  = (const float*)d_in[11];
    const float* Wc  = (const float*)d_in[12];
    const float* bc  = (const float*)d_in[13];

    const int n = in_sizes[0] / 512;
    const int E = in_sizes[1] / 2;
    const int total = E + n;
    const int* srcA = ei;
    const int* dstA = ei + E;

    float *xl, *xr;
    __nv_bfloat16 *xh, *xlo, *hh, *hl, *h1h, *h1l, *h2h, *h2l;
    __nv_bfloat16 *Wlt_h, *Wlt_l, *Wrt_h, *Wrt_l, *W1t_h, *W1t_l, *W2t_h, *W2t_l, *Wct_h, *Wct_l;
    cudaGetSymbolAddress((void**)&xl,  g_xl);
    cudaGetSymbolAddress((void**)&xr,  g_xr);
    cudaGetSymbolAddress((void**)&xh,  g_xh);
    cudaGetSymbolAddress((void**)&xlo, g_xlo);
    cudaGetSymbolAddress((void**)&hh,  g_hh);
    cudaGetSymbolAddress((void**)&hl,  g_hl);
    cudaGetSymbolAddress((void**)&h1h, g_h1h);
    cudaGetSymbolAddress((void**)&h1l, g_h1l);
    cudaGetSymbolAddress((void**)&h2h, g_h2h);
    cudaGetSymbolAddress((void**)&h2l, g_h2l);
    cudaGetSymbolAddress((void**)&Wlt_h, g_Wlt_h);
    cudaGetSymbolAddress((void**)&Wlt_l, g_Wlt_l);
    cudaGetSymbolAddress((void**)&Wrt_h, g_Wrt_h);
    cudaGetSymbolAddress((void**)&Wrt_l, g_Wrt_l);
    cudaGetSymbolAddress((void**)&W1t_h, g_W1t_h);
    cudaGetSymbolAddress((void**)&W1t_l, g_W1t_l);
    cudaGetSymbolAddress((void**)&W2t_h, g_W2t_h);
    cudaGetSymbolAddress((void**)&W2t_l, g_W2t_l);
    cudaGetSymbolAddress((void**)&Wct_h, g_Wct_h);
    cudaGetSymbolAddress((void**)&Wct_l, g_Wct_l);
    float* out = (float*)d_out;

    cudaFuncSetAttribute(gemm_mma<false, true, false>,
                         cudaFuncAttributeMaxDynamicSharedMemorySize, GSMEM);
    cudaFuncSetAttribute(gemm_mma<true, false, true>,
                         cudaFuncAttributeMaxDynamicSharedMemorySize, GSMEM);

    // conversions
    int n4 = n * 512 / 4;
    split_x_kernel<<<(n4 + 255) / 256, 256>>>((const float4*)x,
                                              (__nv_bfloat162*)xh, (__nv_bfloat162*)xlo, n4);
    dim3 tb(32, 8);
    tsplit_kernel<<<dim3(1024 / 32, 512 / 32), tb>>>(Wl, Wlt_h, Wlt_l, 512, 1024);
    tsplit_kernel<<<dim3(1024 / 32, 512 / 32), tb>>>(Wr, Wrt_h, Wrt_l, 512, 1024);
    tsplit_kernel<<<dim3(512 / 32, 1024 / 32), tb>>>(W1, W1t_h, W1t_l, 1024, 512);
    tsplit_kernel<<<dim3(128 / 32, 512 / 32), tb>>>(W2, W2t_h, W2t_l, 512, 128);
    tsplit_kernel<<<dim3(4, 4), tb>>>(Wc, Wct_h, Wct_l, 128, 100);

    init_kernel<<<(n + 255) / 256, 256>>>(n);

    // xl / xr transforms (fp32 out, no relu)
    dim3 gx(1024 / 128, (n + 127) / 128);
    gemm_mma<false, true, false><<<gx, 256, GSMEM>>>(xh, xlo, Wlt_h, Wlt_l, bl,
                                                     xl, nullptr, nullptr, n, 1024, 512);
    gemm_mma<false, true, false><<<gx, 256, GSMEM>>>(xh, xlo, Wrt_h, Wrt_l, br,
                                                     xr, nullptr, nullptr, n, 1024, 512);

    count_kernel<<<(E + 255) / 256, 256>>>(dstA, E);
    scan_kernel<<<1, 1024>>>(n);
    fill_kernel<<<(total + 255) / 256, 256>>>(dstA, E, total);

    // fused edge-score + softmax + aggregate
    agg_fused_kernel<<<n, 256>>>(srcA, att, cb, E);

    // MLP head
    dim3 g1(512 / 128, (n + 127) / 128);
    gemm_mma<true, false, true><<<g1, 256, GSMEM>>>(hh, hl, W1t_h, W1t_l, b1,
                                                    nullptr, h1h, h1l, n, 512, 1024);
    dim3 g2(1, (n + 127) / 128);
    gemm_mma<true, false, true><<<g2, 256, GSMEM>>>(h1h, h1l, W2t_h, W2t_l, b2,
                                                    nullptr, h2h, h2l, n, 128, 512);
    dim3 g3(1, (n + 127) / 128);
    gemm_mma<false, true, false><<<g3, 256, GSMEM>>>(h2h, h2l, Wct_h, Wct_l, bc,
                                                     out, nullptr, nullptr, n, 100, 128);
}

// round 7
// speedup vs baseline: 1.1774x; 1.1774x over previous
#include <cuda_runtime.h>
#include <cuda_bf16.h>
#include <cstdint>

#define HID 1024
#define NEG_SLOPE 0.2f

static const int NMAX = 10240;
static const int EMAX = 163840;
#define TMAX (EMAX + NMAX)

// ---------------- scratch (static device globals) ----------------
__device__ __align__(16) float g_xl[(size_t)NMAX * HID];
__device__ __align__(16) float g_xr[(size_t)NMAX * HID];
__device__ __align__(16) float g_e [TMAX];
__device__ int   g_deg[NMAX];
__device__ int   g_cur[NMAX];
__device__ int   g_off[NMAX + 1];
__device__ int   g_csr[TMAX];

// bf16 hi/lo split activations
__device__ __align__(16) __nv_bfloat16 g_xh [(size_t)NMAX * 512];
__device__ __align__(16) __nv_bfloat16 g_xlo[(size_t)NMAX * 512];
__device__ __align__(16) __nv_bfloat16 g_hh [(size_t)NMAX * HID];
__device__ __align__(16) __nv_bfloat16 g_hl [(size_t)NMAX * HID];
__device__ __align__(16) __nv_bfloat16 g_h1h[(size_t)NMAX * 512];
__device__ __align__(16) __nv_bfloat16 g_h1l[(size_t)NMAX * 512];
__device__ __align__(16) __nv_bfloat16 g_h2h[(size_t)NMAX * 128];
__device__ __align__(16) __nv_bfloat16 g_h2l[(size_t)NMAX * 128];

// transposed + split weights: Wt[n][k]; Wl and Wr concatenated along n
__device__ __align__(16) __nv_bfloat16 g_Wlrt_h[2048 * 512], g_Wlrt_l[2048 * 512];
__device__ __align__(16) __nv_bfloat16 g_W1t_h[512 * 1024], g_W1t_l[512 * 1024];
__device__ __align__(16) __nv_bfloat16 g_W2t_h[128 * 512],  g_W2t_l[128 * 512];
__device__ __align__(16) __nv_bfloat16 g_Wct_h[112 * 128],  g_Wct_l[112 * 128];

// ---------------- PTX helpers (plain compute_103 ISA only) ----------------
__device__ __forceinline__ uint32_t smem_u32(const void* p) {
    uint32_t a;
    asm("{ .reg .u64 t; cvta.to.shared.u64 t, %1; cvt.u32.u64 %0, t; }"
        : "=r"(a) : "l"(p));
    return a;
}
__device__ __forceinline__ void cp16(uint32_t saddr, const void* gaddr, int srcsize) {
    asm volatile("cp.async.cg.shared.global [%0], [%1], 16, %2;"
                 :: "r"(saddr), "l"(gaddr), "r"(srcsize) : "memory");
}
#define CP_COMMIT() asm volatile("cp.async.commit_group;" ::: "memory")
#define CP_WAIT(n)  asm volatile("cp.async.wait_group %0;" :: "n"(n) : "memory")

__device__ __forceinline__ void ldsm4(uint32_t& r0, uint32_t& r1, uint32_t& r2,
                                      uint32_t& r3, uint32_t a) {
    asm volatile("ldmatrix.sync.aligned.m8n8.x4.shared.b16 {%0,%1,%2,%3}, [%4];"
                 : "=r"(r0), "=r"(r1), "=r"(r2), "=r"(r3) : "r"(a));
}
__device__ __forceinline__ void mma16816(float* d, const uint32_t* a,
                                         uint32_t b0, uint32_t b1) {
    asm volatile(
        "mma.sync.aligned.m16n8k16.row.col.f32.bf16.bf16.f32 "
        "{%0,%1,%2,%3}, {%4,%5,%6,%7}, {%8,%9}, {%0,%1,%2,%3};"
        : "+f"(d[0]), "+f"(d[1]), "+f"(d[2]), "+f"(d[3])
        : "r"(a[0]), "r"(a[1]), "r"(a[2]), "r"(a[3]), "r"(b0), "r"(b1));
}

// ============================================================================
// bf16-split GEMM on mma.sync (round-4 winner, + SPLITC dual-output mode)
// ============================================================================
#define TILE_B   8192
#define STAGE_B  (4 * TILE_B)
#define GSMEM    (2 * STAGE_B)

__device__ __forceinline__ void fill_tile_async(
    uint32_t dst, const __nv_bfloat16* __restrict__ src,
    int rowbase, int limit, int K, int k0, int tid)
{
    int fr = tid >> 2;
    int fc = tid & 3;
#pragma unroll
    for (int it = 0; it < 2; it++) {
        int row = fr + it * 64;
        int grow = rowbase + row;
        uint32_t saddr = dst + row * 64 + ((fc ^ ((row >> 1) & 3)) * 16);
        const void* g = src + (size_t)grow * K + k0 + fc * 8;
        cp16(saddr, g, (grow < limit) ? 16 : 0);
    }
}

template <bool RELU, bool WF32, bool WBF16, bool SPLITC>
__global__ __launch_bounds__(256, 1)
void gemm_mma(const __nv_bfloat16* __restrict__ Ah, const __nv_bfloat16* __restrict__ Al,
              const __nv_bfloat16* __restrict__ Bh, const __nv_bfloat16* __restrict__ Bl,
              const float* __restrict__ bias, const float* __restrict__ bias2,
              float* __restrict__ C, float* __restrict__ C2,
              __nv_bfloat16* __restrict__ Ch, __nv_bfloat16* __restrict__ Cl,
              int M, int Nn, int K)
{
    extern __shared__ char smem[];
    const uint32_t sb = smem_u32(smem);
    const int tid = threadIdx.x;
    const int wid = tid >> 5;
    const int lane = tid & 31;
    const int row0 = blockIdx.y * 128;
    const int col0 = blockIdx.x * 128;
    const int wm0 = (wid & 3) * 32;
    const int wn0 = (wid >> 2) * 64;

    float acc[2][8][4];
#pragma unroll
    for (int i = 0; i < 2; i++)
#pragma unroll
        for (int j = 0; j < 8; j++)
#pragma unroll
            for (int k = 0; k < 4; k++) acc[i][j][k] = 0.f;

    uint32_t aoff[2][2], boff[4][2];
#pragma unroll
    for (int mt = 0; mt < 2; mt++) {
        int arow = wm0 + mt * 16 + (lane & 15);
        int hi = lane >> 4;
#pragma unroll
        for (int s = 0; s < 2; s++) {
            int chunk = s * 2 + hi;
            aoff[mt][s] = arow * 64 + ((chunk ^ ((arow >> 1) & 3)) * 16);
        }
    }
#pragma unroll
    for (int bt = 0; bt < 4; bt++) {
        int brow = wn0 + bt * 16 + (lane & 7) + ((lane >> 4) & 1) * 8;
        int hi = (lane >> 3) & 1;
#pragma unroll
        for (int s = 0; s < 2; s++) {
            int chunk = s * 2 + hi;
            boff[bt][s] = brow * 64 + ((chunk ^ ((brow >> 1) & 3)) * 16);
        }
    }

    const int nC = K / 32;

    {
        uint32_t st = sb;
        fill_tile_async(st + 0 * TILE_B, Ah, row0, M,  K, 0, tid);
        fill_tile_async(st + 1 * TILE_B, Al, row0, M,  K, 0, tid);
        fill_tile_async(st + 2 * TILE_B, Bh, col0, Nn, K, 0, tid);
        fill_tile_async(st + 3 * TILE_B, Bl, col0, Nn, K, 0, tid);
        CP_COMMIT();
    }

    for (int c = 0; c < nC; c++) {
        const uint32_t st = sb + (c & 1) * STAGE_B;
        if (c + 1 < nC) {
            uint32_t nx = sb + ((c + 1) & 1) * STAGE_B;
            int k0 = (c + 1) * 32;
            fill_tile_async(nx + 0 * TILE_B, Ah, row0, M,  K, k0, tid);
            fill_tile_async(nx + 1 * TILE_B, Al, row0, M,  K, k0, tid);
            fill_tile_async(nx + 2 * TILE_B, Bh, col0, Nn, K, k0, tid);
            fill_tile_async(nx + 3 * TILE_B, Bl, col0, Nn, K, k0, tid);
            CP_COMMIT();
            CP_WAIT(1);
        } else {
            CP_WAIT(0);
        }
        __syncthreads();

#pragma unroll
        for (int s = 0; s < 2; s++) {
            uint32_t ah[2][4], al[2][4], bh[4][4], bl[4][4];
#pragma unroll
            for (int mt = 0; mt < 2; mt++) {
                ldsm4(ah[mt][0], ah[mt][1], ah[mt][2], ah[mt][3],
                      st + 0 * TILE_B + aoff[mt][s]);
                ldsm4(al[mt][0], al[mt][1], al[mt][2], al[mt][3],
                      st + 1 * TILE_B + aoff[mt][s]);
            }
#pragma unroll
            for (int bt = 0; bt < 4; bt++) {
                ldsm4(bh[bt][0], bh[bt][1], bh[bt][2], bh[bt][3],
                      st + 2 * TILE_B + boff[bt][s]);
                ldsm4(bl[bt][0], bl[bt][1], bl[bt][2], bl[bt][3],
                      st + 3 * TILE_B + boff[bt][s]);
            }
#pragma unroll
            for (int mt = 0; mt < 2; mt++) {
#pragma unroll
                for (int bt = 0; bt < 4; bt++) {
                    mma16816(acc[mt][2 * bt + 0], ah[mt], bh[bt][0], bh[bt][1]);
                    mma16816(acc[mt][2 * bt + 1], ah[mt], bh[bt][2], bh[bt][3]);
                    mma16816(acc[mt][2 * bt + 0], ah[mt], bl[bt][0], bl[bt][1]);
                    mma16816(acc[mt][2 * bt + 1], ah[mt], bl[bt][2], bl[bt][3]);
                    mma16816(acc[mt][2 * bt + 0], al[mt], bh[bt][0], bh[bt][1]);
                    mma16816(acc[mt][2 * bt + 1], al[mt], bh[bt][2], bh[bt][3]);
                }
            }
        }
        __syncthreads();
    }

#pragma unroll
    for (int mt = 0; mt < 2; mt++) {
#pragma unroll
        for (int nt = 0; nt < 8; nt++) {
            int col = col0 + wn0 + nt * 8 + (lane & 3) * 2;
            if (col >= Nn) continue;
            const float* bp = bias;
            float* Cp = C;
            int ccol = col;
            int cw = Nn;
            if (SPLITC) {
                cw = 1024;
                if (col >= 1024) { bp = bias2; Cp = C2; ccol = col - 1024; }
            }
            float bx = bp[ccol], by = bp[ccol + 1];
#pragma unroll
            for (int half = 0; half < 2; half++) {
                int grow = row0 + wm0 + mt * 16 + (lane >> 2) + half * 8;
                if (grow >= M) continue;
                float ox = acc[mt][nt][half * 2 + 0] + bx;
                float oy = acc[mt][nt][half * 2 + 1] + by;
                if (RELU) { ox = fmaxf(ox, 0.f); oy = fmaxf(oy, 0.f); }
                if (WF32) {
                    *(float2*)(Cp + (size_t)grow * cw + ccol) = make_float2(ox, oy);
                }
                if (WBF16) {
                    size_t idx = (size_t)grow * Nn + col;
                    __nv_bfloat16 hx = __float2bfloat16(ox);
                    __nv_bfloat16 hy = __float2bfloat16(oy);
                    *(__nv_bfloat162*)(Ch + idx) = __nv_bfloat162(hx, hy);
                    *(__nv_bfloat162*)(Cl + idx) = __floats2bfloat162_rn(
                        ox - __bfloat162float(hx), oy - __bfloat162float(hy));
                }
            }
        }
    }
}

// ============================================================================
// Conversions
// ============================================================================
__global__ void split_x_kernel(const float4* __restrict__ src,
                               __nv_bfloat162* __restrict__ h2,
                               __nv_bfloat162* __restrict__ l2, int n4)
{
    int i = blockIdx.x * blockDim.x + threadIdx.x;
    if (i >= n4) return;
    float4 v = src[i];
    __nv_bfloat16 hx = __float2bfloat16(v.x), hy = __float2bfloat16(v.y);
    __nv_bfloat16 hz = __float2bfloat16(v.z), hw = __float2bfloat16(v.w);
    h2[i * 2 + 0] = __floats2bfloat162_rn(v.x, v.y);
    h2[i * 2 + 1] = __floats2bfloat162_rn(v.z, v.w);
    l2[i * 2 + 0] = __floats2bfloat162_rn(v.x - __bfloat162float(hx), v.y - __bfloat162float(hy));
    l2[i * 2 + 1] = __floats2bfloat162_rn(v.z - __bfloat162float(hz), v.w - __bfloat162float(hw));
}

__global__ void tsplit_kernel(const float* __restrict__ W,
                              __nv_bfloat16* __restrict__ th, __nv_bfloat16* __restrict__ tl,
                              int K, int N)
{
    __shared__ float t[32][33];
    int k0 = blockIdx.y * 32, n0 = blockIdx.x * 32;
    int tx = threadIdx.x, ty = threadIdx.y;
#pragma unroll
    for (int i = 0; i < 4; i++) {
        int k = k0 + ty + i * 8;
        t[ty + i * 8][tx] = (k < K && n0 + tx < N) ? W[(size_t)k * N + n0 + tx] : 0.f;
    }
    __syncthreads();
#pragma unroll
    for (int i = 0; i < 4; i++) {
        int n = n0 + ty + i * 8;
        int k = k0 + tx;
        if (n < N && k < K) {
            float v = t[tx][ty + i * 8];
            __nv_bfloat16 hb = __float2bfloat16(v);
            th[(size_t)n * K + k] = hb;
            tl[(size_t)n * K + k] = __float2bfloat16(v - __bfloat162float(hb));
        }
    }
}

// ============================================================================
// CSR build
// ============================================================================
__global__ void init_kernel(int n) {
    int i = blockIdx.x * blockDim.x + threadIdx.x;
    if (i < n) { g_deg[i] = 1; g_cur[i] = 0; }
}
__global__ void count_kernel(const int* __restrict__ dst, int E) {
    int k = blockIdx.x * blockDim.x + threadIdx.x;
    if (k < E) atomicAdd(&g_deg[dst[k]], 1);
}
__global__ __launch_bounds__(1024)
void scan_kernel(int n) {
    __shared__ int part[1024];
    int tid = threadIdx.x;
    int chunk = (n + 1023) >> 10;
    int beg = tid * chunk;
    int end = min(beg + chunk, n);
    int s = 0;
    for (int i = beg; i < end; i++) s += g_deg[i];
    part[tid] = s;
    __syncthreads();
    for (int d = 1; d < 1024; d <<= 1) {
        int v = part[tid];
        int a = (tid >= d) ? part[tid - d] : 0;
        __syncthreads();
        part[tid] = v + a;
        __syncthreads();
    }
    int run = (tid > 0) ? part[tid - 1] : 0;
    for (int i = beg; i < end; i++) { g_off[i] = run; run += g_deg[i]; }
    if (tid == 1023) g_off[n] = part[1023];
}
__global__ void fill_kernel(const int* __restrict__ dst, int E, int total) {
    int k = blockIdx.x * blockDim.x + threadIdx.x;
    if (k >= total) return;
    int d = (k < E) ? dst[k] : (k - E);
    int pos = atomicAdd(&g_cur[d], 1);
    g_csr[g_off[d] + pos] = k;
}

// ============================================================================
// Edge scores (round-4 structure: massively parallel warp-per-edge)
// ============================================================================
__global__ __launch_bounds__(256)
void edge_e_kernel(const int* __restrict__ src, const int* __restrict__ dst,
                   const float* __restrict__ att, int E, int total)
{
    int w = blockIdx.x * 8 + (threadIdx.x >> 5);
    if (w >= total) return;
    int lane = threadIdx.x & 31;
    int s = (w < E) ? src[w] : (w - E);
    int d = (w < E) ? dst[w] : (w - E);
    const float4* xl4 = (const float4*)(g_xl + (size_t)s * HID);
    const float4* xr4 = (const float4*)(g_xr + (size_t)d * HID);
    const float4* at4 = (const float4*)att;
    float acc = 0.f;
#pragma unroll
    for (int j = 0; j < 8; j++) {
        int idx = lane + j * 32;
        float4 a = xl4[idx];
        float4 b = xr4[idx];
        float4 t = at4[idx];
        float v;
        v = a.x + b.x; v = (v > 0.f) ? v : NEG_SLOPE * v; acc = fmaf(v, t.x, acc);
        v = a.y + b.y; v = (v > 0.f) ? v : NEG_SLOPE * v; acc = fmaf(v, t.y, acc);
        v = a.z + b.z; v = (v > 0.f) ? v : NEG_SLOPE * v; acc = fmaf(v, t.z, acc);
        v = a.w + b.w; v = (v > 0.f) ? v : NEG_SLOPE * v; acc = fmaf(v, t.w, acc);
    }
#pragma unroll
    for (int o = 16; o > 0; o >>= 1) acc += __shfl_xor_sync(0xffffffffu, acc, o);
    if (lane == 0) g_e[w] = acc;
}

// ============================================================================
// Segment softmax + aggregation (round-4 structure, pass-2 unrolled x4)
// ============================================================================
#define DEGCAP 1024
__global__ __launch_bounds__(256)
void aggregate_kernel(const int* __restrict__ src,
                      const float* __restrict__ conv_b, int E)
{
    int node = blockIdx.x;
    int tid = threadIdx.x;
    int beg = g_off[node];
    int deg = g_off[node + 1] - beg;

    __shared__ float s_w[DEGCAP];
    __shared__ int   s_src[DEGCAP];
    __shared__ float red[256];

    float m, ssum;
    float4 acc = make_float4(0.f, 0.f, 0.f, 0.f);

    if (deg <= DEGCAP) {
        for (int j = tid; j < deg; j += 256) {
            int k = g_csr[beg + j];
            s_w[j] = g_e[k];
            s_src[j] = (k < E) ? src[k] : (k - E);
        }
        __syncthreads();
        float mx = -1e30f;
        for (int j = tid; j < deg; j += 256) mx = fmaxf(mx, s_w[j]);
        red[tid] = mx; __syncthreads();
        for (int o = 128; o > 0; o >>= 1) {
            if (tid < o) red[tid] = fmaxf(red[tid], red[tid + o]);
            __syncthreads();
        }
        m = red[0];
        __syncthreads();
        for (int j = tid; j < deg; j += 256) s_w[j] = __expf(s_w[j] - m);
        float sl = 0.f;
        for (int j = tid; j < deg; j += 256) sl += s_w[j];
        red[tid] = sl; __syncthreads();
        for (int o = 128; o > 0; o >>= 1) {
            if (tid < o) red[tid] += red[tid + o];
            __syncthreads();
        }
        ssum = red[0];
        __syncthreads();
        // pass 2: unrolled x4 for MLP
        int j = 0;
        for (; j + 3 < deg; j += 4) {
            float w0 = s_w[j + 0], w1 = s_w[j + 1], w2 = s_w[j + 2], w3 = s_w[j + 3];
            const float4* r0 = (const float4*)(g_xl + (size_t)s_src[j + 0] * HID);
            const float4* r1 = (const float4*)(g_xl + (size_t)s_src[j + 1] * HID);
            const float4* r2 = (const float4*)(g_xl + (size_t)s_src[j + 2] * HID);
            const float4* r3 = (const float4*)(g_xl + (size_t)s_src[j + 3] * HID);
            float4 v0 = r0[tid], v1 = r1[tid], v2 = r2[tid], v3 = r3[tid];
            acc.x = fmaf(w0, v0.x, acc.x); acc.y = fmaf(w0, v0.y, acc.y);
            acc.z = fmaf(w0, v0.z, acc.z); acc.w = fmaf(w0, v0.w, acc.w);
            acc.x = fmaf(w1, v1.x, acc.x); acc.y = fmaf(w1, v1.y, acc.y);
            acc.z = fmaf(w1, v1.z, acc.z); acc.w = fmaf(w1, v1.w, acc.w);
            acc.x = fmaf(w2, v2.x, acc.x); acc.y = fmaf(w2, v2.y, acc.y);
            acc.z = fmaf(w2, v2.z, acc.z); acc.w = fmaf(w2, v2.w, acc.w);
            acc.x = fmaf(w3, v3.x, acc.x); acc.y = fmaf(w3, v3.y, acc.y);
            acc.z = fmaf(w3, v3.z, acc.z); acc.w = fmaf(w3, v3.w, acc.w);
        }
        for (; j < deg; j++) {
            float wgt = s_w[j];
            const float4* row = (const float4*)(g_xl + (size_t)s_src[j] * HID);
            float4 v = row[tid];
            acc.x = fmaf(wgt, v.x, acc.x);
            acc.y = fmaf(wgt, v.y, acc.y);
            acc.z = fmaf(wgt, v.z, acc.z);
            acc.w = fmaf(wgt, v.w, acc.w);
        }
    } else {
        float mx = -1e30f;
        for (int j = tid; j < deg; j += 256) mx = fmaxf(mx, g_e[g_csr[beg + j]]);
        red[tid] = mx; __syncthreads();
        for (int o = 128; o > 0; o >>= 1) {
            if (tid < o) red[tid] = fmaxf(red[tid], red[tid + o]);
            __syncthreads();
        }
        m = red[0];
        __syncthreads();
        float sl = 0.f;
        for (int j = tid; j < deg; j += 256) sl += __expf(g_e[g_csr[beg + j]] - m);
        red[tid] = sl; __syncthreads();
        for (int o = 128; o > 0; o >>= 1) {
            if (tid < o) red[tid] += red[tid + o];
            __syncthreads();
        }
        ssum = red[0];
        __syncthreads();
        for (int j = 0; j < deg; j++) {
            int k = g_csr[beg + j];
            float wgt = __expf(g_e[k] - m);
            int sidx = (k < E) ? src[k] : (k - E);
            const float4* row = (const float4*)(g_xl + (size_t)sidx * HID);
            float4 v = row[tid];
            acc.x = fmaf(wgt, v.x, acc.x);
            acc.y = fmaf(wgt, v.y, acc.y);
            acc.z = fmaf(wgt, v.z, acc.z);
            acc.w = fmaf(wgt, v.w, acc.w);
        }
    }

    float inv = 1.f / ssum;
    float4 cb = ((const float4*)conv_b)[tid];
    float4 o;
    o.x = fmaxf(fmaf(acc.x, inv, cb.x), 0.f);
    o.y = fmaxf(fmaf(acc.y, inv, cb.y), 0.f);
    o.z = fmaxf(fmaf(acc.z, inv, cb.z), 0.f);
    o.w = fmaxf(fmaf(acc.w, inv, cb.w), 0.f);

    size_t base = (size_t)node * HID + tid * 4;
    __nv_bfloat16 hx = __float2bfloat16(o.x), hy = __float2bfloat16(o.y);
    __nv_bfloat16 hz = __float2bfloat16(o.z), hw = __float2bfloat16(o.w);
    __nv_bfloat162* hh2 = (__nv_bfloat162*)(g_hh + base);
    __nv_bfloat162* hl2 = (__nv_bfloat162*)(g_hl + base);
    hh2[0] = __floats2bfloat162_rn(o.x, o.y);
    hh2[1] = __floats2bfloat162_rn(o.z, o.w);
    hl2[0] = __floats2bfloat162_rn(o.x - __bfloat162float(hx), o.y - __bfloat162float(hy));
    hl2[1] = __floats2bfloat162_rn(o.z - __bfloat162float(hz), o.w - __bfloat162float(hw));
}

// ============================================================================
// launch
// ============================================================================
extern "C" void kernel_launch(void* const* d_in, const int* in_sizes, int n_in,
                              void* d_out, int out_size)
{
    const float* x   = (const float*)d_in[0];
    const int*   ei  = (const int*)d_in[1];
    const float* Wl  = (const float*)d_in[2];
    const float* bl  = (const float*)d_in[3];
    const float* Wr  = (const float*)d_in[4];
    const float* br  = (const float*)d_in[5];
    const float* att = (const float*)d_in[6];
    const float* cb  = (const float*)d_in[7];
    const float* W1  = (const float*)d_in[8];
    const float* b1  = (const float*)d_in[9];
    const float* W2  = (const float*)d_in[10];
    const float* b2  = (const float*)d_in[11];
    const float* Wc  = (const float*)d_in[12];
    const float* bc  = (const float*)d_in[13];

    const int n = in_sizes[0] / 512;
    const int E = in_sizes[1] / 2;
    const int total = E + n;
    const int* srcA = ei;
    const int* dstA = ei + E;

    float *xl, *xr;
    __nv_bfloat16 *xh, *xlo, *hh, *hl, *h1h, *h1l, *h2h, *h2l;
    __nv_bfloat16 *Wlrt_h, *Wlrt_l, *W1t_h, *W1t_l, *W2t_h, *W2t_l, *Wct_h, *Wct_l;
    cudaGetSymbolAddress((void**)&xl,  g_xl);
    cudaGetSymbolAddress((void**)&xr,  g_xr);
    cudaGetSymbolAddress((void**)&xh,  g_xh);
    cudaGetSymbolAddress((void**)&xlo, g_xlo);
    cudaGetSymbolAddress((void**)&hh,  g_hh);
    cudaGetSymbolAddress((void**)&hl,  g_hl);
    cudaGetSymbolAddress((void**)&h1h, g_h1h);
    cudaGetSymbolAddress((void**)&h1l, g_h1l);
    cudaGetSymbolAddress((void**)&h2h, g_h2h);
    cudaGetSymbolAddress((void**)&h2l, g_h2l);
    cudaGetSymbolAddress((void**)&Wlrt_h, g_Wlrt_h);
    cudaGetSymbolAddress((void**)&Wlrt_l, g_Wlrt_l);
    cudaGetSymbolAddress((void**)&W1t_h, g_W1t_h);
    cudaGetSymbolAddress((void**)&W1t_l, g_W1t_l);
    cudaGetSymbolAddress((void**)&W2t_h, g_W2t_h);
    cudaGetSymbolAddress((void**)&W2t_l, g_W2t_l);
    cudaGetSymbolAddress((void**)&Wct_h, g_Wct_h);
    cudaGetSymbolAddress((void**)&Wct_l, g_Wct_l);
    float* out = (float*)d_out;

    cudaFuncSetAttribute(gemm_mma<false, true, false, true>,
                         cudaFuncAttributeMaxDynamicSharedMemorySize, GSMEM);
    cudaFuncSetAttribute(gemm_mma<false, true, false, false>,
                         cudaFuncAttributeMaxDynamicSharedMemorySize, GSMEM);
    cudaFuncSetAttribute(gemm_mma<true, false, true, false>,
                         cudaFuncAttributeMaxDynamicSharedMemorySize, GSMEM);

    // conversions
    int n4 = n * 512 / 4;
    split_x_kernel<<<(n4 + 255) / 256, 256>>>((const float4*)x,
                                              (__nv_bfloat162*)xh, (__nv_bfloat162*)xlo, n4);
    dim3 tb(32, 8);
    // Wl -> rows 0..1023 of Wlrt, Wr -> rows 1024..2047
    tsplit_kernel<<<dim3(1024 / 32, 512 / 32), tb>>>(Wl, Wlrt_h, Wlrt_l, 512, 1024);
    tsplit_kernel<<<dim3(1024 / 32, 512 / 32), tb>>>(Wr, Wlrt_h + 1024 * 512,
                                                     Wlrt_l + 1024 * 512, 512, 1024);
    tsplit_kernel<<<dim3(512 / 32, 1024 / 32), tb>>>(W1, W1t_h, W1t_l, 1024, 512);
    tsplit_kernel<<<dim3(128 / 32, 512 / 32), tb>>>(W2, W2t_h, W2t_l, 512, 128);
    tsplit_kernel<<<dim3(4, 4), tb>>>(Wc, Wct_h, Wct_l, 128, 100);

    init_kernel<<<(n + 255) / 256, 256>>>(n);

    // combined xl|xr transform: one GEMM, Nn=2048, dual fp32 outputs
    dim3 gx(2048 / 128, (n + 127) / 128);
    gemm_mma<false, true, false, true><<<gx, 256, GSMEM>>>(
        xh, xlo, Wlrt_h, Wlrt_l, bl, br, xl, xr, nullptr, nullptr, n, 2048, 512);

    count_kernel<<<(E + 255) / 256, 256>>>(dstA, E);
    scan_kernel<<<1, 1024>>>(n);
    fill_kernel<<<(total + 255) / 256, 256>>>(dstA, E, total);

    edge_e_kernel<<<(total + 7) / 8, 256>>>(srcA, dstA, att, E, total);
    aggregate_kernel<<<n, 256>>>(srcA, cb, E);

    // MLP head
    dim3 g1(512 / 128, (n + 127) / 128);
    gemm_mma<true, false, true, false><<<g1, 256, GSMEM>>>(
        hh, hl, W1t_h, W1t_l, b1, nullptr, nullptr, nullptr, h1h, h1l, n, 512, 1024);
    dim3 g2(1, (n + 127) / 128);
    gemm_mma<true, false, true, false><<<g2, 256, GSMEM>>>(
        h1h, h1l, W2t_h, W2t_l, b2, nullptr, nullptr, nullptr, h2h, h2l, n, 128, 512);
    dim3 g3(1, (n + 127) / 128);
    gemm_mma<false, true, false, false><<<g3, 256, GSMEM>>>(
        h2h, h2l, Wct_h, Wct_l, bc, nullptr, out, nullptr, nullptr, nullptr, n, 100, 128);
}

// round 8
// speedup vs baseline: 1.1933x; 1.0135x over previous
#include <cuda_runtime.h>
#include <cuda_bf16.h>
#include <cstdint>

#define HID 1024
#define NEG_SLOPE 0.2f

static const int NMAX = 10240;
static const int EMAX = 163840;
#define TMAX (EMAX + NMAX)

// ---------------- scratch (static device globals) ----------------
__device__ __align__(16) float g_xl[(size_t)NMAX * HID];
__device__ __align__(16) float g_xr[(size_t)NMAX * HID];
__device__ __align__(16) float g_e [TMAX];
__device__ int   g_deg[NMAX];
__device__ int   g_cur[NMAX];
__device__ int   g_off[NMAX + 1];
__device__ int   g_srcs[TMAX];   // src node per CSR position
__device__ int   g_dsts[TMAX];   // dst node per CSR position

// bf16 hi/lo split activations
__device__ __align__(16) __nv_bfloat16 g_xh [(size_t)NMAX * 512];
__device__ __align__(16) __nv_bfloat16 g_xlo[(size_t)NMAX * 512];
__device__ __align__(16) __nv_bfloat16 g_hh [(size_t)NMAX * HID];
__device__ __align__(16) __nv_bfloat16 g_hl [(size_t)NMAX * HID];
__device__ __align__(16) __nv_bfloat16 g_h1h[(size_t)NMAX * 512];
__device__ __align__(16) __nv_bfloat16 g_h1l[(size_t)NMAX * 512];
__device__ __align__(16) __nv_bfloat16 g_h2h[(size_t)NMAX * 128];
__device__ __align__(16) __nv_bfloat16 g_h2l[(size_t)NMAX * 128];

// transposed + split weights: Wt[n][k]; Wl and Wr concatenated along n
__device__ __align__(16) __nv_bfloat16 g_Wlrt_h[2048 * 512], g_Wlrt_l[2048 * 512];
__device__ __align__(16) __nv_bfloat16 g_W1t_h[512 * 1024], g_W1t_l[512 * 1024];
__device__ __align__(16) __nv_bfloat16 g_W2t_h[128 * 512],  g_W2t_l[128 * 512];
__device__ __align__(16) __nv_bfloat16 g_Wct_h[112 * 128],  g_Wct_l[112 * 128];

// ---------------- PTX helpers (plain compute_103 ISA only) ----------------
__device__ __forceinline__ uint32_t smem_u32(const void* p) {
    uint32_t a;
    asm("{ .reg .u64 t; cvta.to.shared.u64 t, %1; cvt.u32.u64 %0, t; }"
        : "=r"(a) : "l"(p));
    return a;
}
__device__ __forceinline__ void cp16(uint32_t saddr, const void* gaddr, int srcsize) {
    asm volatile("cp.async.cg.shared.global [%0], [%1], 16, %2;"
                 :: "r"(saddr), "l"(gaddr), "r"(srcsize) : "memory");
}
#define CP_COMMIT() asm volatile("cp.async.commit_group;" ::: "memory")
#define CP_WAIT(n)  asm volatile("cp.async.wait_group %0;" :: "n"(n) : "memory")

__device__ __forceinline__ void ldsm4(uint32_t& r0, uint32_t& r1, uint32_t& r2,
                                      uint32_t& r3, uint32_t a) {
    asm volatile("ldmatrix.sync.aligned.m8n8.x4.shared.b16 {%0,%1,%2,%3}, [%4];"
                 : "=r"(r0), "=r"(r1), "=r"(r2), "=r"(r3) : "r"(a));
}
__device__ __forceinline__ void mma16816(float* d, const uint32_t* a,
                                         uint32_t b0, uint32_t b1) {
    asm volatile(
        "mma.sync.aligned.m16n8k16.row.col.f32.bf16.bf16.f32 "
        "{%0,%1,%2,%3}, {%4,%5,%6,%7}, {%8,%9}, {%0,%1,%2,%3};"
        : "+f"(d[0]), "+f"(d[1]), "+f"(d[2]), "+f"(d[3])
        : "r"(a[0]), "r"(a[1]), "r"(a[2]), "r"(a[3]), "r"(b0), "r"(b1));
}

// ============================================================================
// bf16-split GEMM on mma.sync (round-7 winner, unchanged)
// ============================================================================
#define TILE_B   8192
#define STAGE_B  (4 * TILE_B)
#define GSMEM    (2 * STAGE_B)

__device__ __forceinline__ void fill_tile_async(
    uint32_t dst, const __nv_bfloat16* __restrict__ src,
    int rowbase, int limit, int K, int k0, int tid)
{
    int fr = tid >> 2;
    int fc = tid & 3;
#pragma unroll
    for (int it = 0; it < 2; it++) {
        int row = fr + it * 64;
        int grow = rowbase + row;
        uint32_t saddr = dst + row * 64 + ((fc ^ ((row >> 1) & 3)) * 16);
        const void* g = src + (size_t)grow * K + k0 + fc * 8;
        cp16(saddr, g, (grow < limit) ? 16 : 0);
    }
}

template <bool RELU, bool WF32, bool WBF16, bool SPLITC>
__global__ __launch_bounds__(256, 1)
void gemm_mma(const __nv_bfloat16* __restrict__ Ah, const __nv_bfloat16* __restrict__ Al,
              const __nv_bfloat16* __restrict__ Bh, const __nv_bfloat16* __restrict__ Bl,
              const float* __restrict__ bias, const float* __restrict__ bias2,
              float* __restrict__ C, float* __restrict__ C2,
              __nv_bfloat16* __restrict__ Ch, __nv_bfloat16* __restrict__ Cl,
              int M, int Nn, int K)
{
    extern __shared__ char smem[];
    const uint32_t sb = smem_u32(smem);
    const int tid = threadIdx.x;
    const int wid = tid >> 5;
    const int lane = tid & 31;
    const int row0 = blockIdx.y * 128;
    const int col0 = blockIdx.x * 128;
    const int wm0 = (wid & 3) * 32;
    const int wn0 = (wid >> 2) * 64;

    float acc[2][8][4];
#pragma unroll
    for (int i = 0; i < 2; i++)
#pragma unroll
        for (int j = 0; j < 8; j++)
#pragma unroll
            for (int k = 0; k < 4; k++) acc[i][j][k] = 0.f;

    uint32_t aoff[2][2], boff[4][2];
#pragma unroll
    for (int mt = 0; mt < 2; mt++) {
        int arow = wm0 + mt * 16 + (lane & 15);
        int hi = lane >> 4;
#pragma unroll
        for (int s = 0; s < 2; s++) {
            int chunk = s * 2 + hi;
            aoff[mt][s] = arow * 64 + ((chunk ^ ((arow >> 1) & 3)) * 16);
        }
    }
#pragma unroll
    for (int bt = 0; bt < 4; bt++) {
        int brow = wn0 + bt * 16 + (lane & 7) + ((lane >> 4) & 1) * 8;
        int hi = (lane >> 3) & 1;
#pragma unroll
        for (int s = 0; s < 2; s++) {
            int chunk = s * 2 + hi;
            boff[bt][s] = brow * 64 + ((chunk ^ ((brow >> 1) & 3)) * 16);
        }
    }

    const int nC = K / 32;

    {
        uint32_t st = sb;
        fill_tile_async(st + 0 * TILE_B, Ah, row0, M,  K, 0, tid);
        fill_tile_async(st + 1 * TILE_B, Al, row0, M,  K, 0, tid);
        fill_tile_async(st + 2 * TILE_B, Bh, col0, Nn, K, 0, tid);
        fill_tile_async(st + 3 * TILE_B, Bl, col0, Nn, K, 0, tid);
        CP_COMMIT();
    }

    for (int c = 0; c < nC; c++) {
        const uint32_t st = sb + (c & 1) * STAGE_B;
        if (c + 1 < nC) {
            uint32_t nx = sb + ((c + 1) & 1) * STAGE_B;
            int k0 = (c + 1) * 32;
            fill_tile_async(nx + 0 * TILE_B, Ah, row0, M,  K, k0, tid);
            fill_tile_async(nx + 1 * TILE_B, Al, row0, M,  K, k0, tid);
            fill_tile_async(nx + 2 * TILE_B, Bh, col0, Nn, K, k0, tid);
            fill_tile_async(nx + 3 * TILE_B, Bl, col0, Nn, K, k0, tid);
            CP_COMMIT();
            CP_WAIT(1);
        } else {
            CP_WAIT(0);
        }
        __syncthreads();

#pragma unroll
        for (int s = 0; s < 2; s++) {
            uint32_t ah[2][4], al[2][4], bh[4][4], bl[4][4];
#pragma unroll
            for (int mt = 0; mt < 2; mt++) {
                ldsm4(ah[mt][0], ah[mt][1], ah[mt][2], ah[mt][3],
                      st + 0 * TILE_B + aoff[mt][s]);
                ldsm4(al[mt][0], al[mt][1], al[mt][2], al[mt][3],
                      st + 1 * TILE_B + aoff[mt][s]);
            }
#pragma unroll
            for (int bt = 0; bt < 4; bt++) {
                ldsm4(bh[bt][0], bh[bt][1], bh[bt][2], bh[bt][3],
                      st + 2 * TILE_B + boff[bt][s]);
                ldsm4(bl[bt][0], bl[bt][1], bl[bt][2], bl[bt][3],
                      st + 3 * TILE_B + boff[bt][s]);
            }
#pragma unroll
            for (int mt = 0; mt < 2; mt++) {
#pragma unroll
                for (int bt = 0; bt < 4; bt++) {
                    mma16816(acc[mt][2 * bt + 0], ah[mt], bh[bt][0], bh[bt][1]);
                    mma16816(acc[mt][2 * bt + 1], ah[mt], bh[bt][2], bh[bt][3]);
                    mma16816(acc[mt][2 * bt + 0], ah[mt], bl[bt][0], bl[bt][1]);
                    mma16816(acc[mt][2 * bt + 1], ah[mt], bl[bt][2], bl[bt][3]);
                    mma16816(acc[mt][2 * bt + 0], al[mt], bh[bt][0], bh[bt][1]);
                    mma16816(acc[mt][2 * bt + 1], al[mt], bh[bt][2], bh[bt][3]);
                }
            }
        }
        __syncthreads();
    }

#pragma unroll
    for (int mt = 0; mt < 2; mt++) {
#pragma unroll
        for (int nt = 0; nt < 8; nt++) {
            int col = col0 + wn0 + nt * 8 + (lane & 3) * 2;
            if (col >= Nn) continue;
            const float* bp = bias;
            float* Cp = C;
            int ccol = col;
            int cw = Nn;
            if (SPLITC) {
                cw = 1024;
                if (col >= 1024) { bp = bias2; Cp = C2; ccol = col - 1024; }
            }
            float bx = bp[ccol], by = bp[ccol + 1];
#pragma unroll
            for (int half = 0; half < 2; half++) {
                int grow = row0 + wm0 + mt * 16 + (lane >> 2) + half * 8;
                if (grow >= M) continue;
                float ox = acc[mt][nt][half * 2 + 0] + bx;
                float oy = acc[mt][nt][half * 2 + 1] + by;
                if (RELU) { ox = fmaxf(ox, 0.f); oy = fmaxf(oy, 0.f); }
                if (WF32) {
                    *(float2*)(Cp + (size_t)grow * cw + ccol) = make_float2(ox, oy);
                }
                if (WBF16) {
                    size_t idx = (size_t)grow * Nn + col;
                    __nv_bfloat16 hx = __float2bfloat16(ox);
                    __nv_bfloat16 hy = __float2bfloat16(oy);
                    *(__nv_bfloat162*)(Ch + idx) = __nv_bfloat162(hx, hy);
                    *(__nv_bfloat162*)(Cl + idx) = __floats2bfloat162_rn(
                        ox - __bfloat162float(hx), oy - __bfloat162float(hy));
                }
            }
        }
    }
}

// ============================================================================
// Conversions
// ============================================================================
__global__ void split_x_kernel(const float4* __restrict__ src,
                               __nv_bfloat162* __restrict__ h2,
                               __nv_bfloat162* __restrict__ l2, int n4)
{
    int i = blockIdx.x * blockDim.x + threadIdx.x;
    if (i >= n4) return;
    float4 v = src[i];
    __nv_bfloat16 hx = __float2bfloat16(v.x), hy = __float2bfloat16(v.y);
    __nv_bfloat16 hz = __float2bfloat16(v.z), hw = __float2bfloat16(v.w);
    h2[i * 2 + 0] = __floats2bfloat162_rn(v.x, v.y);
    h2[i * 2 + 1] = __floats2bfloat162_rn(v.z, v.w);
    l2[i * 2 + 0] = __floats2bfloat162_rn(v.x - __bfloat162float(hx), v.y - __bfloat162float(hy));
    l2[i * 2 + 1] = __floats2bfloat162_rn(v.z - __bfloat162float(hz), v.w - __bfloat162float(hw));
}

// one 32x32 transpose+split tile; callable from the batched prep kernel
__device__ __forceinline__ void tsplit_block(
    const float* __restrict__ W, __nv_bfloat16* __restrict__ th,
    __nv_bfloat16* __restrict__ tl, int K, int N, int bx, int by, int tid)
{
    __shared__ float t[32][33];
    int k0 = by * 32, n0 = bx * 32;
    int tx = tid & 31, ty = tid >> 5;
#pragma unroll
    for (int i = 0; i < 4; i++) {
        int k = k0 + ty + i * 8;
        t[ty + i * 8][tx] = (k < K && n0 + tx < N) ? W[(size_t)k * N + n0 + tx] : 0.f;
    }
    __syncthreads();
#pragma unroll
    for (int i = 0; i < 4; i++) {
        int n = n0 + ty + i * 8;
        int k = k0 + tx;
        if (n < N && k < K) {
            float v = t[tx][ty + i * 8];
            __nv_bfloat16 hb = __float2bfloat16(v);
            th[(size_t)n * K + k] = hb;
            tl[(size_t)n * K + k] = __float2bfloat16(v - __bfloat162float(hb));
        }
    }
}

// batched: all 5 weight splits + deg/cur init, single launch
__global__ __launch_bounds__(256)
void prep_kernel(const float* __restrict__ Wl, const float* __restrict__ Wr,
                 const float* __restrict__ W1, const float* __restrict__ W2,
                 const float* __restrict__ Wc,
                 __nv_bfloat16* Wlrt_h, __nv_bfloat16* Wlrt_l,
                 __nv_bfloat16* W1t_h, __nv_bfloat16* W1t_l,
                 __nv_bfloat16* W2t_h, __nv_bfloat16* W2t_l,
                 __nv_bfloat16* Wct_h, __nv_bfloat16* Wct_l,
                 int n)
{
    int b = blockIdx.x;
    int tid = threadIdx.x;
    if (b < 512) {              // Wl: grid 32 x 16
        tsplit_block(Wl, Wlrt_h, Wlrt_l, 512, 1024, b & 31, b >> 5, tid);
    } else if (b < 1024) {      // Wr
        int bb = b - 512;
        tsplit_block(Wr, Wlrt_h + 1024 * 512, Wlrt_l + 1024 * 512,
                     512, 1024, bb & 31, bb >> 5, tid);
    } else if (b < 1536) {      // W1: grid 16 x 32
        int bb = b - 1024;
        tsplit_block(W1, W1t_h, W1t_l, 1024, 512, bb & 15, bb >> 4, tid);
    } else if (b < 1600) {      // W2: grid 4 x 16
        int bb = b - 1536;
        tsplit_block(W2, W2t_h, W2t_l, 512, 128, bb & 3, bb >> 2, tid);
    } else if (b < 1616) {      // Wc: grid 4 x 4
        int bb = b - 1600;
        tsplit_block(Wc, Wct_h, Wct_l, 128, 100, bb & 3, bb >> 2, tid);
    } else {                    // deg/cur init
        int i = (b - 1616) * 256 + tid;
        if (i < n) { g_deg[i] = 1; g_cur[i] = 0; }
    }
}

// ============================================================================
// CSR build (emits dst-sorted src/dst arrays)
// ============================================================================
__global__ void count_kernel(const int* __restrict__ dst, int E) {
    int k = blockIdx.x * blockDim.x + threadIdx.x;
    if (k < E) atomicAdd(&g_deg[dst[k]], 1);
}
__global__ __launch_bounds__(1024)
void scan_kernel(int n) {
    __shared__ int part[1024];
    int tid = threadIdx.x;
    int chunk = (n + 1023) >> 10;
    int beg = tid * chunk;
    int end = min(beg + chunk, n);
    int s = 0;
    for (int i = beg; i < end; i++) s += g_deg[i];
    part[tid] = s;
    __syncthreads();
    for (int d = 1; d < 1024; d <<= 1) {
        int v = part[tid];
        int a = (tid >= d) ? part[tid - d] : 0;
        __syncthreads();
        part[tid] = v + a;
        __syncthreads();
    }
    int run = (tid > 0) ? part[tid - 1] : 0;
    for (int i = beg; i < end; i++) { g_off[i] = run; run += g_deg[i]; }
    if (tid == 1023) g_off[n] = part[1023];
}
__global__ void fill_kernel(const int* __restrict__ src, const int* __restrict__ dst,
                            int E, int total) {
    int k = blockIdx.x * blockDim.x + threadIdx.x;
    if (k >= total) return;
    int d = (k < E) ? dst[k] : (k - E);
    int s = (k < E) ? src[k] : (k - E);
    int pos = atomicAdd(&g_cur[d], 1);
    int p = g_off[d] + pos;
    g_srcs[p] = s;
    g_dsts[p] = d;
}

// ============================================================================
// Edge scores over dst-sorted positions: consecutive warps share xr[dst] (L1)
// ============================================================================
__global__ __launch_bounds__(256)
void edge_e_kernel(const float* __restrict__ att, int total)
{
    int w = blockIdx.x * 8 + (threadIdx.x >> 5);
    if (w >= total) return;
    int lane = threadIdx.x & 31;
    int s = g_srcs[w];
    int d = g_dsts[w];
    const float4* xl4 = (const float4*)(g_xl + (size_t)s * HID);
    const float4* xr4 = (const float4*)(g_xr + (size_t)d * HID);
    const float4* at4 = (const float4*)att;
    float acc = 0.f;
#pragma unroll
    for (int j = 0; j < 8; j++) {
        int idx = lane + j * 32;
        float4 a = xl4[idx];
        float4 b = xr4[idx];
        float4 t = at4[idx];
        float v;
        v = a.x + b.x; v = (v > 0.f) ? v : NEG_SLOPE * v; acc = fmaf(v, t.x, acc);
        v = a.y + b.y; v = (v > 0.f) ? v : NEG_SLOPE * v; acc = fmaf(v, t.y, acc);
        v = a.z + b.z; v = (v > 0.f) ? v : NEG_SLOPE * v; acc = fmaf(v, t.z, acc);
        v = a.w + b.w; v = (v > 0.f) ? v : NEG_SLOPE * v; acc = fmaf(v, t.w, acc);
    }
#pragma unroll
    for (int o = 16; o > 0; o >>= 1) acc += __shfl_xor_sync(0xffffffffu, acc, o);
    if (lane == 0) g_e[w] = acc;
}

// ============================================================================
// Segment softmax + aggregation (contiguous sorted reads, pass-2 x4 unroll)
// ============================================================================
#define DEGCAP 1024
__global__ __launch_bounds__(256)
void aggregate_kernel(const float* __restrict__ conv_b)
{
    int node = blockIdx.x;
    int tid = threadIdx.x;
    int beg = g_off[node];
    int deg = g_off[node + 1] - beg;

    __shared__ float s_w[DEGCAP];
    __shared__ int   s_src[DEGCAP];
    __shared__ float red[256];

    float m, ssum;
    float4 acc = make_float4(0.f, 0.f, 0.f, 0.f);

    if (deg <= DEGCAP) {
        for (int j = tid; j < deg; j += 256) {
            s_w[j] = g_e[beg + j];
            s_src[j] = g_srcs[beg + j];
        }
        __syncthreads();
        float mx = -1e30f;
        for (int j = tid; j < deg; j += 256) mx = fmaxf(mx, s_w[j]);
        red[tid] = mx; __syncthreads();
        for (int o = 128; o > 0; o >>= 1) {
            if (tid < o) red[tid] = fmaxf(red[tid], red[tid + o]);
            __syncthreads();
        }
        m = red[0];
        __syncthreads();
        for (int j = tid; j < deg; j += 256) s_w[j] = __expf(s_w[j] - m);
        float sl = 0.f;
        for (int j = tid; j < deg; j += 256) sl += s_w[j];
        red[tid] = sl; __syncthreads();
        for (int o = 128; o > 0; o >>= 1) {
            if (tid < o) red[tid] += red[tid + o];
            __syncthreads();
        }
        ssum = red[0];
        __syncthreads();
        int j = 0;
        for (; j + 3 < deg; j += 4) {
            float w0 = s_w[j + 0], w1 = s_w[j + 1], w2 = s_w[j + 2], w3 = s_w[j + 3];
            const float4* r0 = (const float4*)(g_xl + (size_t)s_src[j + 0] * HID);
            const float4* r1 = (const float4*)(g_xl + (size_t)s_src[j + 1] * HID);
            const float4* r2 = (const float4*)(g_xl + (size_t)s_src[j + 2] * HID);
            const float4* r3 = (const float4*)(g_xl + (size_t)s_src[j + 3] * HID);
            float4 v0 = r0[tid], v1 = r1[tid], v2 = r2[tid], v3 = r3[tid];
            acc.x = fmaf(w0, v0.x, acc.x); acc.y = fmaf(w0, v0.y, acc.y);
            acc.z = fmaf(w0, v0.z, acc.z); acc.w = fmaf(w0, v0.w, acc.w);
            acc.x = fmaf(w1, v1.x, acc.x); acc.y = fmaf(w1, v1.y, acc.y);
            acc.z = fmaf(w1, v1.z, acc.z); acc.w = fmaf(w1, v1.w, acc.w);
            acc.x = fmaf(w2, v2.x, acc.x); acc.y = fmaf(w2, v2.y, acc.y);
            acc.z = fmaf(w2, v2.z, acc.z); acc.w = fmaf(w2, v2.w, acc.w);
            acc.x = fmaf(w3, v3.x, acc.x); acc.y = fmaf(w3, v3.y, acc.y);
            acc.z = fmaf(w3, v3.z, acc.z); acc.w = fmaf(w3, v3.w, acc.w);
        }
        for (; j < deg; j++) {
            float wgt = s_w[j];
            const float4* row = (const float4*)(g_xl + (size_t)s_src[j] * HID);
            float4 v = row[tid];
            acc.x = fmaf(wgt, v.x, acc.x);
            acc.y = fmaf(wgt, v.y, acc.y);
            acc.z = fmaf(wgt, v.z, acc.z);
            acc.w = fmaf(wgt, v.w, acc.w);
        }
    } else {
        float mx = -1e30f;
        for (int j = tid; j < deg; j += 256) mx = fmaxf(mx, g_e[beg + j]);
        red[tid] = mx; __syncthreads();
        for (int o = 128; o > 0; o >>= 1) {
            if (tid < o) red[tid] = fmaxf(red[tid], red[tid + o]);
            __syncthreads();
        }
        m = red[0];
        __syncthreads();
        float sl = 0.f;
        for (int j = tid; j < deg; j += 256) sl += __expf(g_e[beg + j] - m);
        red[tid] = sl; __syncthreads();
        for (int o = 128; o > 0; o >>= 1) {
            if (tid < o) red[tid] += red[tid + o];
            __syncthreads();
        }
        ssum = red[0];
        __syncthreads();
        for (int j = 0; j < deg; j++) {
            float wgt = __expf(g_e[beg + j] - m);
            const float4* row = (const float4*)(g_xl + (size_t)g_srcs[beg + j] * HID);
            float4 v = row[tid];
            acc.x = fmaf(wgt, v.x, acc.x);
            acc.y = fmaf(wgt, v.y, acc.y);
            acc.z = fmaf(wgt, v.z, acc.z);
            acc.w = fmaf(wgt, v.w, acc.w);
        }
    }

    float inv = 1.f / ssum;
    float4 cb = ((const float4*)conv_b)[tid];
    float4 o;
    o.x = fmaxf(fmaf(acc.x, inv, cb.x), 0.f);
    o.y = fmaxf(fmaf(acc.y, inv, cb.y), 0.f);
    o.z = fmaxf(fmaf(acc.z, inv, cb.z), 0.f);
    o.w = fmaxf(fmaf(acc.w, inv, cb.w), 0.f);

    size_t base = (size_t)node * HID + tid * 4;
    __nv_bfloat16 hx = __float2bfloat16(o.x), hy = __float2bfloat16(o.y);
    __nv_bfloat16 hz = __float2bfloat16(o.z), hw = __float2bfloat16(o.w);
    __nv_bfloat162* hh2 = (__nv_bfloat162*)(g_hh + base);
    __nv_bfloat162* hl2 = (__nv_bfloat162*)(g_hl + base);
    hh2[0] = __floats2bfloat162_rn(o.x, o.y);
    hh2[1] = __floats2bfloat162_rn(o.z, o.w);
    hl2[0] = __floats2bfloat162_rn(o.x - __bfloat162float(hx), o.y - __bfloat162float(hy));
    hl2[1] = __floats2bfloat162_rn(o.z - __bfloat162float(hz), o.w - __bfloat162float(hw));
}

// ============================================================================
// launch
// ============================================================================
extern "C" void kernel_launch(void* const* d_in, const int* in_sizes, int n_in,
                              void* d_out, int out_size)
{
    const float* x   = (const float*)d_in[0];
    const int*   ei  = (const int*)d_in[1];
    const float* Wl  = (const float*)d_in[2];
    const float* bl  = (const float*)d_in[3];
    const float* Wr  = (const float*)d_in[4];
    const float* br  = (const float*)d_in[5];
    const float* att = (const float*)d_in[6];
    const float* cb  = (const float*)d_in[7];
    const float* W1  = (const float*)d_in[8];
    const float* b1  = (const float*)d_in[9];
    const float* W2  = (const float*)d_in[10];
    const float* b2  = (const float*)d_in[11];
    const float* Wc  = (const float*)d_in[12];
    const float* bc  = (const float*)d_in[13];

    const int n = in_sizes[0] / 512;
    const int E = in_sizes[1] / 2;
    const int total = E + n;
    const int* srcA = ei;
    const int* dstA = ei + E;

    float *xl, *xr;
    __nv_bfloat16 *xh, *xlo, *hh, *hl, *h1h, *h1l, *h2h, *h2l;
    __nv_bfloat16 *Wlrt_h, *Wlrt_l, *W1t_h, *W1t_l, *W2t_h, *W2t_l, *Wct_h, *Wct_l;
    cudaGetSymbolAddress((void**)&xl,  g_xl);
    cudaGetSymbolAddress((void**)&xr,  g_xr);
    cudaGetSymbolAddress((void**)&xh,  g_xh);
    cudaGetSymbolAddress((void**)&xlo, g_xlo);
    cudaGetSymbolAddress((void**)&hh,  g_hh);
    cudaGetSymbolAddress((void**)&hl,  g_hl);
    cudaGetSymbolAddress((void**)&h1h, g_h1h);
    cudaGetSymbolAddress((void**)&h1l, g_h1l);
    cudaGetSymbolAddress((void**)&h2h, g_h2h);
    cudaGetSymbolAddress((void**)&h2l, g_h2l);
    cudaGetSymbolAddress((void**)&Wlrt_h, g_Wlrt_h);
    cudaGetSymbolAddress((void**)&Wlrt_l, g_Wlrt_l);
    cudaGetSymbolAddress((void**)&W1t_h, g_W1t_h);
    cudaGetSymbolAddress((void**)&W1t_l, g_W1t_l);
    cudaGetSymbolAddress((void**)&W2t_h, g_W2t_h);
    cudaGetSymbolAddress((void**)&W2t_l, g_W2t_l);
    cudaGetSymbolAddress((void**)&Wct_h, g_Wct_h);
    cudaGetSymbolAddress((void**)&Wct_l, g_Wct_l);
    float* out = (float*)d_out;

    cudaFuncSetAttribute(gemm_mma<false, true, false, true>,
                         cudaFuncAttributeMaxDynamicSharedMemorySize, GSMEM);
    cudaFuncSetAttribute(gemm_mma<false, true, false, false>,
                         cudaFuncAttributeMaxDynamicSharedMemorySize, GSMEM);
    cudaFuncSetAttribute(gemm_mma<true, false, true, false>,
                         cudaFuncAttributeMaxDynamicSharedMemorySize, GSMEM);

    // conversions (split_x + one batched prep launch)
    int n4 = n * 512 / 4;
    split_x_kernel<<<(n4 + 255) / 256, 256>>>((const float4*)x,
                                              (__nv_bfloat162*)xh, (__nv_bfloat162*)xlo, n4);
    int initBlocks = (n + 255) / 256;
    prep_kernel<<<1616 + initBlocks, 256>>>(Wl, Wr, W1, W2, Wc,
                                            Wlrt_h, Wlrt_l, W1t_h, W1t_l,
                                            W2t_h, W2t_l, Wct_h, Wct_l, n);

    // combined xl|xr transform: one GEMM, Nn=2048, dual fp32 outputs
    dim3 gx(2048 / 128, (n + 127) / 128);
    gemm_mma<false, true, false, true><<<gx, 256, GSMEM>>>(
        xh, xlo, Wlrt_h, Wlrt_l, bl, br, xl, xr, nullptr, nullptr, n, 2048, 512);

    count_kernel<<<(E + 255) / 256, 256>>>(dstA, E);
    scan_kernel<<<1, 1024>>>(n);
    fill_kernel<<<(total + 255) / 256, 256>>>(srcA, dstA, E, total);

    edge_e_kernel<<<(total + 7) / 8, 256>>>(att, total);
    aggregate_kernel<<<n, 256>>>(cb);

    // MLP head
    dim3 g1(512 / 128, (n + 127) / 128);
    gemm_mma<true, false, true, false><<<g1, 256, GSMEM>>>(
        hh, hl, W1t_h, W1t_l, b1, nullptr, nullptr, nullptr, h1h, h1l, n, 512, 1024);
    dim3 g2(1, (n + 127) / 128);
    gemm_mma<true, false, true, false><<<g2, 256, GSMEM>>>(
        h1h, h1l, W2t_h, W2t_l, b2, nullptr, nullptr, nullptr, h2h, h2l, n, 128, 512);
    dim3 g3(1, (n + 127) / 128);
    gemm_mma<false, true, false, false><<<g3, 256, GSMEM>>>(
        h2h, h2l, Wct_h, Wct_l, bc, nullptr, out, nullptr, nullptr, nullptr, n, 100, 128);
}

// round 12
// speedup vs baseline: 1.4385x; 1.2055x over previous
#include <cuda_runtime.h>
#include <cuda_bf16.h>
#include <cuda_fp16.h>
#include <cstdint>

#define HID 1024
#define NEG_SLOPE 0.2f

static const int NMAX = 10240;
static const int EMAX = 163840;
#define TMAX (EMAX + NMAX)

// ---------------- scratch (static device globals) ----------------
__device__ __align__(16) float g_xl[(size_t)NMAX * HID];
__device__ __align__(16) float g_xr[(size_t)NMAX * HID];
__device__ __align__(16) float g_e [TMAX];
__device__ int   g_deg[NMAX];
__device__ int   g_cur[NMAX];
__device__ int   g_off[NMAX + 1];
__device__ int   g_srcs[TMAX];
__device__ int   g_dsts[TMAX];

// fp16 single-precision-split activations (2-term path)
__device__ __align__(16) __half g_xh[(size_t)NMAX * 512];
__device__ __align__(16) __half g_hh[(size_t)NMAX * HID];
// bf16 hi/lo activations (3-term path for W2/Wc)
__device__ __align__(16) __nv_bfloat16 g_h1h[(size_t)NMAX * 512];
__device__ __align__(16) __nv_bfloat16 g_h1l[(size_t)NMAX * 512];
__device__ __align__(16) __nv_bfloat16 g_h2h[(size_t)NMAX * 128];
__device__ __align__(16) __nv_bfloat16 g_h2l[(size_t)NMAX * 128];

// transposed + split weights: Wt[n][k]
__device__ __align__(16) __half g_Wlrt_h[2048 * 512], g_Wlrt_l[2048 * 512];   // fp16 hi/lo
__device__ __align__(16) __half g_W1t_h[512 * 1024],  g_W1t_l[512 * 1024];    // fp16 hi/lo
__device__ __align__(16) __nv_bfloat16 g_W2t_h[128 * 512], g_W2t_l[128 * 512];
__device__ __align__(16) __nv_bfloat16 g_Wct_h[112 * 128], g_Wct_l[112 * 128];

// ---------------- PTX helpers ----------------
__device__ __forceinline__ uint32_t smem_u32(const void* p) {
    uint32_t a;
    asm("{ .reg .u64 t; cvta.to.shared.u64 t, %1; cvt.u32.u64 %0, t; }"
        : "=r"(a) : "l"(p));
    return a;
}
__device__ __forceinline__ void cp16(uint32_t saddr, const void* gaddr, int srcsize) {
    asm volatile("cp.async.cg.shared.global [%0], [%1], 16, %2;"
                 :: "r"(saddr), "l"(gaddr), "r"(srcsize) : "memory");
}
#define CP_COMMIT() asm volatile("cp.async.commit_group;" ::: "memory")
#define CP_WAIT(n)  asm volatile("cp.async.wait_group %0;" :: "n"(n) : "memory")

__device__ __forceinline__ void ldsm4(uint32_t& r0, uint32_t& r1, uint32_t& r2,
                                      uint32_t& r3, uint32_t a) {
    asm volatile("ldmatrix.sync.aligned.m8n8.x4.shared.b16 {%0,%1,%2,%3}, [%4];"
                 : "=r"(r0), "=r"(r1), "=r"(r2), "=r"(r3) : "r"(a));
}
__device__ __forceinline__ void mma_bf16(float* d, const uint32_t* a,
                                         uint32_t b0, uint32_t b1) {
    asm volatile(
        "mma.sync.aligned.m16n8k16.row.col.f32.bf16.bf16.f32 "
        "{%0,%1,%2,%3}, {%4,%5,%6,%7}, {%8,%9}, {%0,%1,%2,%3};"
        : "+f"(d[0]), "+f"(d[1]), "+f"(d[2]), "+f"(d[3])
        : "r"(a[0]), "r"(a[1]), "r"(a[2]), "r"(a[3]), "r"(b0), "r"(b1));
}
__device__ __forceinline__ void mma_f16(float* d, const uint32_t* a,
                                        uint32_t b0, uint32_t b1) {
    asm volatile(
        "mma.sync.aligned.m16n8k16.row.col.f32.f16.f16.f32 "
        "{%0,%1,%2,%3}, {%4,%5,%6,%7}, {%8,%9}, {%0,%1,%2,%3};"
        : "+f"(d[0]), "+f"(d[1]), "+f"(d[2]), "+f"(d[3])
        : "r"(a[0]), "r"(a[1]), "r"(a[2]), "r"(a[3]), "r"(b0), "r"(b1));
}

// shared tile geometry (2-byte elements, 128 rows x 64B, swizzled chunks)
#define TILE_B   8192

__device__ __forceinline__ void fill_tile_async(
    uint32_t dst, const void* __restrict__ src2B,
    int rowbase, int limit, int K, int k0, int tid)
{
    int fr = tid >> 2;
    int fc = tid & 3;
#pragma unroll
    for (int it = 0; it < 2; it++) {
        int row = fr + it * 64;
        int grow = rowbase + row;
        uint32_t saddr = dst + row * 64 + ((fc ^ ((row >> 1) & 3)) * 16);
        const char* g = (const char*)src2B + ((size_t)grow * K + k0 + fc * 8) * 2;
        cp16(saddr, g, (grow < limit) ? 16 : 0);
    }
}

// ============================================================================
// bf16 3-term GEMM (round-7 winner; used for W2, Wc)
// ============================================================================
#define STAGE_B  (4 * TILE_B)
#define GSMEM    (2 * STAGE_B)

template <bool RELU, bool WF32, bool WBF16, bool SPLITC>
__global__ __launch_bounds__(256, 1)
void gemm_mma(const __nv_bfloat16* __restrict__ Ah, const __nv_bfloat16* __restrict__ Al,
              const __nv_bfloat16* __restrict__ Bh, const __nv_bfloat16* __restrict__ Bl,
              const float* __restrict__ bias, const float* __restrict__ bias2,
              float* __restrict__ C, float* __restrict__ C2,
              __nv_bfloat16* __restrict__ Ch, __nv_bfloat16* __restrict__ Cl,
              int M, int Nn, int K)
{
    extern __shared__ char smem[];
    const uint32_t sb = smem_u32(smem);
    const int tid = threadIdx.x;
    const int wid = tid >> 5;
    const int lane = tid & 31;
    const int row0 = blockIdx.y * 128;
    const int col0 = blockIdx.x * 128;
    const int wm0 = (wid & 3) * 32;
    const int wn0 = (wid >> 2) * 64;

    float acc[2][8][4];
#pragma unroll
    for (int i = 0; i < 2; i++)
#pragma unroll
        for (int j = 0; j < 8; j++)
#pragma unroll
            for (int k = 0; k < 4; k++) acc[i][j][k] = 0.f;

    uint32_t aoff[2][2], boff[4][2];
#pragma unroll
    for (int mt = 0; mt < 2; mt++) {
        int arow = wm0 + mt * 16 + (lane & 15);
        int hi = lane >> 4;
#pragma unroll
        for (int s = 0; s < 2; s++) {
            int chunk = s * 2 + hi;
            aoff[mt][s] = arow * 64 + ((chunk ^ ((arow >> 1) & 3)) * 16);
        }
    }
#pragma unroll
    for (int bt = 0; bt < 4; bt++) {
        int brow = wn0 + bt * 16 + (lane & 7) + ((lane >> 4) & 1) * 8;
        int hi = (lane >> 3) & 1;
#pragma unroll
        for (int s = 0; s < 2; s++) {
            int chunk = s * 2 + hi;
            boff[bt][s] = brow * 64 + ((chunk ^ ((brow >> 1) & 3)) * 16);
        }
    }

    const int nC = K / 32;
    {
        uint32_t st = sb;
        fill_tile_async(st + 0 * TILE_B, Ah, row0, M,  K, 0, tid);
        fill_tile_async(st + 1 * TILE_B, Al, row0, M,  K, 0, tid);
        fill_tile_async(st + 2 * TILE_B, Bh, col0, Nn, K, 0, tid);
        fill_tile_async(st + 3 * TILE_B, Bl, col0, Nn, K, 0, tid);
        CP_COMMIT();
    }

    for (int c = 0; c < nC; c++) {
        const uint32_t st = sb + (c & 1) * STAGE_B;
        if (c + 1 < nC) {
            uint32_t nx = sb + ((c + 1) & 1) * STAGE_B;
            int k0 = (c + 1) * 32;
            fill_tile_async(nx + 0 * TILE_B, Ah, row0, M,  K, k0, tid);
            fill_tile_async(nx + 1 * TILE_B, Al, row0, M,  K, k0, tid);
            fill_tile_async(nx + 2 * TILE_B, Bh, col0, Nn, K, k0, tid);
            fill_tile_async(nx + 3 * TILE_B, Bl, col0, Nn, K, k0, tid);
            CP_COMMIT();
            CP_WAIT(1);
        } else {
            CP_WAIT(0);
        }
        __syncthreads();

#pragma unroll
        for (int s = 0; s < 2; s++) {
            uint32_t ah[2][4], al[2][4], bh[4][4], bl[4][4];
#pragma unroll
            for (int mt = 0; mt < 2; mt++) {
                ldsm4(ah[mt][0], ah[mt][1], ah[mt][2], ah[mt][3],
                      st + 0 * TILE_B + aoff[mt][s]);
                ldsm4(al[mt][0], al[mt][1], al[mt][2], al[mt][3],
                      st + 1 * TILE_B + aoff[mt][s]);
            }
#pragma unroll
            for (int bt = 0; bt < 4; bt++) {
                ldsm4(bh[bt][0], bh[bt][1], bh[bt][2], bh[bt][3],
                      st + 2 * TILE_B + boff[bt][s]);
                ldsm4(bl[bt][0], bl[bt][1], bl[bt][2], bl[bt][3],
                      st + 3 * TILE_B + boff[bt][s]);
            }
#pragma unroll
            for (int mt = 0; mt < 2; mt++) {
#pragma unroll
                for (int bt = 0; bt < 4; bt++) {
                    mma_bf16(acc[mt][2 * bt + 0], ah[mt], bh[bt][0], bh[bt][1]);
                    mma_bf16(acc[mt][2 * bt + 1], ah[mt], bh[bt][2], bh[bt][3]);
                    mma_bf16(acc[mt][2 * bt + 0], ah[mt], bl[bt][0], bl[bt][1]);
                    mma_bf16(acc[mt][2 * bt + 1], ah[mt], bl[bt][2], bl[bt][3]);
                    mma_bf16(acc[mt][2 * bt + 0], al[mt], bh[bt][0], bh[bt][1]);
                    mma_bf16(acc[mt][2 * bt + 1], al[mt], bh[bt][2], bh[bt][3]);
                }
            }
        }
        __syncthreads();
    }

#pragma unroll
    for (int mt = 0; mt < 2; mt++) {
#pragma unroll
        for (int nt = 0; nt < 8; nt++) {
            int col = col0 + wn0 + nt * 8 + (lane & 3) * 2;
            if (col >= Nn) continue;
            const float* bp = bias;
            float* Cp = C;
            int ccol = col;
            int cw = Nn;
            if (SPLITC) {
                cw = 1024;
                if (col >= 1024) { bp = bias2; Cp = C2; ccol = col - 1024; }
            }
            float bx = bp[ccol], by = bp[ccol + 1];
#pragma unroll
            for (int half = 0; half < 2; half++) {
                int grow = row0 + wm0 + mt * 16 + (lane >> 2) + half * 8;
                if (grow >= M) continue;
                float ox = acc[mt][nt][half * 2 + 0] + bx;
                float oy = acc[mt][nt][half * 2 + 1] + by;
                if (RELU) { ox = fmaxf(ox, 0.f); oy = fmaxf(oy, 0.f); }
                if (WF32) {
                    *(float2*)(Cp + (size_t)grow * cw + ccol) = make_float2(ox, oy);
                }
                if (WBF16) {
                    size_t idx = (size_t)grow * Nn + col;
                    __nv_bfloat16 hx = __float2bfloat16(ox);
                    __nv_bfloat16 hy = __float2bfloat16(oy);
                    *(__nv_bfloat162*)(Ch + idx) = __nv_bfloat162(hx, hy);
                    *(__nv_bfloat162*)(Cl + idx) = __floats2bfloat162_rn(
                        ox - __bfloat162float(hx), oy - __bfloat162float(hy));
                }
            }
        }
    }
}

// ============================================================================
// fp16 2-term GEMM: D = act(Ah @ (Bh+Bl)^T + bias).  A single fp16, B hi/lo.
// 3 tiles/stage, 2/3 the MMAs of the bf16 path.
// ============================================================================
#define STAGE_H  (3 * TILE_B)
#define GSMEM_H  (2 * STAGE_H)

template <bool RELU, bool WF32, bool WBF16, bool SPLITC>
__global__ __launch_bounds__(256, 1)
void gemm_mma_h(const __half* __restrict__ Ah,
                const __half* __restrict__ Bh, const __half* __restrict__ Bl,
                const float* __restrict__ bias, const float* __restrict__ bias2,
                float* __restrict__ C, float* __restrict__ C2,
                __nv_bfloat16* __restrict__ Ch, __nv_bfloat16* __restrict__ Cl,
                int M, int Nn, int K)
{
    extern __shared__ char smem[];
    const uint32_t sb = smem_u32(smem);
    const int tid = threadIdx.x;
    const int wid = tid >> 5;
    const int lane = tid & 31;
    const int row0 = blockIdx.y * 128;
    const int col0 = blockIdx.x * 128;
    const int wm0 = (wid & 3) * 32;
    const int wn0 = (wid >> 2) * 64;

    float acc[2][8][4];
#pragma unroll
    for (int i = 0; i < 2; i++)
#pragma unroll
        for (int j = 0; j < 8; j++)
#pragma unroll
            for (int k = 0; k < 4; k++) acc[i][j][k] = 0.f;

    uint32_t aoff[2][2], boff[4][2];
#pragma unroll
    for (int mt = 0; mt < 2; mt++) {
        int arow = wm0 + mt * 16 + (lane & 15);
        int hi = lane >> 4;
#pragma unroll
        for (int s = 0; s < 2; s++) {
            int chunk = s * 2 + hi;
            aoff[mt][s] = arow * 64 + ((chunk ^ ((arow >> 1) & 3)) * 16);
        }
    }
#pragma unroll
    for (int bt = 0; bt < 4; bt++) {
        int brow = wn0 + bt * 16 + (lane & 7) + ((lane >> 4) & 1) * 8;
        int hi = (lane >> 3) & 1;
#pragma unroll
        for (int s = 0; s < 2; s++) {
            int chunk = s * 2 + hi;
            boff[bt][s] = brow * 64 + ((chunk ^ ((brow >> 1) & 3)) * 16);
        }
    }

    const int nC = K / 32;
    {
        uint32_t st = sb;
        fill_tile_async(st + 0 * TILE_B, Ah, row0, M,  K, 0, tid);
        fill_tile_async(st + 1 * TILE_B, Bh, col0, Nn, K, 0, tid);
        fill_tile_async(st + 2 * TILE_B, Bl, col0, Nn, K, 0, tid);
        CP_COMMIT();
    }

    for (int c = 0; c < nC; c++) {
        const uint32_t st = sb + (c & 1) * STAGE_H;
        if (c + 1 < nC) {
            uint32_t nx = sb + ((c + 1) & 1) * STAGE_H;
            int k0 = (c + 1) * 32;
            fill_tile_async(nx + 0 * TILE_B, Ah, row0, M,  K, k0, tid);
            fill_tile_async(nx + 1 * TILE_B, Bh, col0, Nn, K, k0, tid);
            fill_tile_async(nx + 2 * TILE_B, Bl, col0, Nn, K, k0, tid);
            CP_COMMIT();
            CP_WAIT(1);
        } else {
            CP_WAIT(0);
        }
        __syncthreads();

#pragma unroll
        for (int s = 0; s < 2; s++) {
            uint32_t ah[2][4], bh[4][4], bl[4][4];
#pragma unroll
            for (int mt = 0; mt < 2; mt++) {
                ldsm4(ah[mt][0], ah[mt][1], ah[mt][2], ah[mt][3],
                      st + 0 * TILE_B + aoff[mt][s]);
            }
#pragma unroll
            for (int bt = 0; bt < 4; bt++) {
                ldsm4(bh[bt][0], bh[bt][1], bh[bt][2], bh[bt][3],
                      st + 1 * TILE_B + boff[bt][s]);
                ldsm4(bl[bt][0], bl[bt][1], bl[bt][2], bl[bt][3],
                      st + 2 * TILE_B + boff[bt][s]);
            }
#pragma unroll
            for (int mt = 0; mt < 2; mt++) {
#pragma unroll
                for (int bt = 0; bt < 4; bt++) {
                    mma_f16(acc[mt][2 * bt + 0], ah[mt], bh[bt][0], bh[bt][1]);
                    mma_f16(acc[mt][2 * bt + 1], ah[mt], bh[bt][2], bh[bt][3]);
                    mma_f16(acc[mt][2 * bt + 0], ah[mt], bl[bt][0], bl[bt][1]);
                    mma_f16(acc[mt][2 * bt + 1], ah[mt], bl[bt][2], bl[bt][3]);
                }
            }
        }
        __syncthreads();
    }

#pragma unroll
    for (int mt = 0; mt < 2; mt++) {
#pragma unroll
        for (int nt = 0; nt < 8; nt++) {
            int col = col0 + wn0 + nt * 8 + (lane & 3) * 2;
            if (col >= Nn) continue;
            const float* bp = bias;
            float* Cp = C;
            int ccol = col;
            int cw = Nn;
            if (SPLITC) {
                cw = 1024;
                if (col >= 1024) { bp = bias2; Cp = C2; ccol = col - 1024; }
            }
            float bx = bp[ccol], by = bp[ccol + 1];
#pragma unroll
            for (int half = 0; half < 2; half++) {
                int grow = row0 + wm0 + mt * 16 + (lane >> 2) + half * 8;
                if (grow >= M) continue;
                float ox = acc[mt][nt][half * 2 + 0] + bx;
                float oy = acc[mt][nt][half * 2 + 1] + by;
                if (RELU) { ox = fmaxf(ox, 0.f); oy = fmaxf(oy, 0.f); }
                if (WF32) {
                    *(float2*)(Cp + (size_t)grow * cw + ccol) = make_float2(ox, oy);
                }
                if (WBF16) {
                    size_t idx = (size_t)grow * Nn + col;
                    __nv_bfloat16 hx = __float2bfloat16(ox);
                    __nv_bfloat16 hy = __float2bfloat16(oy);
                    *(__nv_bfloat162*)(Ch + idx) = __nv_bfloat162(hx, hy);
                    *(__nv_bfloat162*)(Cl + idx) = __floats2bfloat162_rn(
                        ox - __bfloat162float(hx), oy - __bfloat162float(hy));
                }
            }
        }
    }
}

// ============================================================================
// Conversions
// ============================================================================
__global__ void split_x_kernel(const float4* __restrict__ src,
                               __half2* __restrict__ h2, int n4)
{
    int i = blockIdx.x * blockDim.x + threadIdx.x;
    if (i >= n4) return;
    float4 v = src[i];
    h2[i * 2 + 0] = __floats2half2_rn(v.x, v.y);
    h2[i * 2 + 1] = __floats2half2_rn(v.z, v.w);
}

// 32x32 transpose + split tiles (bf16 and fp16 variants)
__device__ __forceinline__ void tsplit_block_bf(
    const float* __restrict__ W, __nv_bfloat16* __restrict__ th,
    __nv_bfloat16* __restrict__ tl, int K, int N, int bx, int by, int tid)
{
    __shared__ float t[32][33];
    int k0 = by * 32, n0 = bx * 32;
    int tx = tid & 31, ty = tid >> 5;
#pragma unroll
    for (int i = 0; i < 4; i++) {
        int k = k0 + ty + i * 8;
        t[ty + i * 8][tx] = (k < K && n0 + tx < N) ? W[(size_t)k * N + n0 + tx] : 0.f;
    }
    __syncthreads();
#pragma unroll
    for (int i = 0; i < 4; i++) {
        int n = n0 + ty + i * 8;
        int k = k0 + tx;
        if (n < N && k < K) {
            float v = t[tx][ty + i * 8];
            __nv_bfloat16 hb = __float2bfloat16(v);
            th[(size_t)n * K + k] = hb;
            tl[(size_t)n * K + k] = __float2bfloat16(v - __bfloat162float(hb));
        }
    }
}
__device__ __forceinline__ void tsplit_block_h(
    const float* __restrict__ W, __half* __restrict__ th,
    __half* __restrict__ tl, int K, int N, int bx, int by, int tid)
{
    __shared__ float t[32][33];
    int k0 = by * 32, n0 = bx * 32;
    int tx = tid & 31, ty = tid >> 5;
#pragma unroll
    for (int i = 0; i < 4; i++) {
        int k = k0 + ty + i * 8;
        t[ty + i * 8][tx] = (k < K && n0 + tx < N) ? W[(size_t)k * N + n0 + tx] : 0.f;
    }
    __syncthreads();
#pragma unroll
    for (int i = 0; i < 4; i++) {
        int n = n0 + ty + i * 8;
        int k = k0 + tx;
        if (n < N && k < K) {
            float v = t[tx][ty + i * 8];
            __half hb = __float2half_rn(v);
            th[(size_t)n * K + k] = hb;
            tl[(size_t)n * K + k] = __float2half_rn(v - __half2float(hb));
        }
    }
}

// batched: all weight splits + deg/cur init, single launch
__global__ __launch_bounds__(256)
void prep_kernel(const float* __restrict__ Wl, const float* __restrict__ Wr,
                 const float* __restrict__ W1, const float* __restrict__ W2,
                 const float* __restrict__ Wc,
                 __half* Wlrt_h, __half* Wlrt_l,
                 __half* W1t_h, __half* W1t_l,
                 __nv_bfloat16* W2t_h, __nv_bfloat16* W2t_l,
                 __nv_bfloat16* Wct_h, __nv_bfloat16* Wct_l,
                 int n)
{
    int b = blockIdx.x;
    int tid = threadIdx.x;
    if (b < 512) {              // Wl: 32 x 16 tiles
        tsplit_block_h(Wl, Wlrt_h, Wlrt_l, 512, 1024, b & 31, b >> 5, tid);
    } else if (b < 1024) {      // Wr
        int bb = b - 512;
        tsplit_block_h(Wr, Wlrt_h + 1024 * 512, Wlrt_l + 1024 * 512,
                       512, 1024, bb & 31, bb >> 5, tid);
    } else if (b < 1536) {      // W1: 16 x 32 tiles
        int bb = b - 1024;
        tsplit_block_h(W1, W1t_h, W1t_l, 1024, 512, bb & 15, bb >> 4, tid);
    } else if (b < 1600) {      // W2: 4 x 16
        int bb = b - 1536;
        tsplit_block_bf(W2, W2t_h, W2t_l, 512, 128, bb & 3, bb >> 2, tid);
    } else if (b < 1616) {      // Wc: 4 x 4
        int bb = b - 1600;
        tsplit_block_bf(Wc, Wct_h, Wct_l, 128, 100, bb & 3, bb >> 2, tid);
    } else {                    // deg/cur init
        int i = (b - 1616) * 256 + tid;
        if (i < n) { g_deg[i] = 1; g_cur[i] = 0; }
    }
}

// ============================================================================
// CSR build
// ============================================================================
__global__ void count_kernel(const int* __restrict__ dst, int E) {
    int k = blockIdx.x * blockDim.x + threadIdx.x;
    if (k < E) atomicAdd(&g_deg[dst[k]], 1);
}
__global__ __launch_bounds__(1024)
void scan_kernel(int n) {
    __shared__ int part[1024];
    int tid = threadIdx.x;
    int chunk = (n + 1023) >> 10;
    int beg = tid * chunk;
    int end = min(beg + chunk, n);
    int s = 0;
    for (int i = beg; i < end; i++) s += g_deg[i];
    part[tid] = s;
    __syncthreads();
    for (int d = 1; d < 1024; d <<= 1) {
        int v = part[tid];
        int a = (tid >= d) ? part[tid - d] : 0;
        __syncthreads();
        part[tid] = v + a;
        __syncthreads();
    }
    int run = (tid > 0) ? part[tid - 1] : 0;
    for (int i = beg; i < end; i++) { g_off[i] = run; run += g_deg[i]; }
    if (tid == 1023) g_off[n] = part[1023];
}
__global__ void fill_kernel(const int* __restrict__ src, const int* __restrict__ dst,
                            int E, int total) {
    int k = blockIdx.x * blockDim.x + threadIdx.x;
    if (k >= total) return;
    int d = (k < E) ? dst[k] : (k - E);
    int s = (k < E) ? src[k] : (k - E);
    int pos = atomicAdd(&g_cur[d], 1);
    int p = g_off[d] + pos;
    g_srcs[p] = s;
    g_dsts[p] = d;
}

// ============================================================================
// Edge scores over dst-sorted positions
// ============================================================================
__global__ __launch_bounds__(256)
void edge_e_kernel(const float* __restrict__ att, int total)
{
    int w = blockIdx.x * 8 + (threadIdx.x >> 5);
    if (w >= total) return;
    int lane = threadIdx.x & 31;
    int s = g_srcs[w];
    int d = g_dsts[w];
    const float4* xl4 = (const float4*)(g_xl + (size_t)s * HID);
    const float4* xr4 = (const float4*)(g_xr + (size_t)d * HID);
    const float4* at4 = (const float4*)att;
    float acc = 0.f;
#pragma unroll
    for (int j = 0; j < 8; j++) {
        int idx = lane + j * 32;
        float4 a = xl4[idx];
        float4 b = xr4[idx];
        float4 t = at4[idx];
        float v;
        v = a.x + b.x; v = (v > 0.f) ? v : NEG_SLOPE * v; acc = fmaf(v, t.x, acc);
        v = a.y + b.y; v = (v > 0.f) ? v : NEG_SLOPE * v; acc = fmaf(v, t.y, acc);
        v = a.z + b.z; v = (v > 0.f) ? v : NEG_SLOPE * v; acc = fmaf(v, t.z, acc);
        v = a.w + b.w; v = (v > 0.f) ? v : NEG_SLOPE * v; acc = fmaf(v, t.w, acc);
    }
#pragma unroll
    for (int o = 16; o > 0; o >>= 1) acc += __shfl_xor_sync(0xffffffffu, acc, o);
    if (lane == 0) g_e[w] = acc;
}

// ============================================================================
// Segment softmax + aggregation; writes h as fp16 single (W1's A operand)
// ============================================================================
#define DEGCAP 1024
__global__ __launch_bounds__(256)
void aggregate_kernel(const float* __restrict__ conv_b)
{
    int node = blockIdx.x;
    int tid = threadIdx.x;
    int beg = g_off[node];
    int deg = g_off[node + 1] - beg;

    __shared__ float s_w[DEGCAP];
    __shared__ int   s_src[DEGCAP];
    __shared__ float red[256];

    float m, ssum;
    float4 acc = make_float4(0.f, 0.f, 0.f, 0.f);

    if (deg <= DEGCAP) {
        for (int j = tid; j < deg; j += 256) {
            s_w[j] = g_e[beg + j];
            s_src[j] = g_srcs[beg + j];
        }
        __syncthreads();
        float mx = -1e30f;
        for (int j = tid; j < deg; j += 256) mx = fmaxf(mx, s_w[j]);
        red[tid] = mx; __syncthreads();
        for (int o = 128; o > 0; o >>= 1) {
            if (tid < o) red[tid] = fmaxf(red[tid], red[tid + o]);
            __syncthreads();
        }
        m = red[0];
        __syncthreads();
        for (int j = tid; j < deg; j += 256) s_w[j] = __expf(s_w[j] - m);
        float sl = 0.f;
        for (int j = tid; j < deg; j += 256) sl += s_w[j];
        red[tid] = sl; __syncthreads();
        for (int o = 128; o > 0; o >>= 1) {
            if (tid < o) red[tid] += red[tid + o];
            __syncthreads();
        }
        ssum = red[0];
        __syncthreads();
        int j = 0;
        for (; j + 3 < deg; j += 4) {
            float w0 = s_w[j + 0], w1 = s_w[j + 1], w2 = s_w[j + 2], w3 = s_w[j + 3];
            const float4* r0 = (const float4*)(g_xl + (size_t)s_src[j + 0] * HID);
            const float4* r1 = (const float4*)(g_xl + (size_t)s_src[j + 1] * HID);
            const float4* r2 = (const float4*)(g_xl + (size_t)s_src[j + 2] * HID);
            const float4* r3 = (const float4*)(g_xl + (size_t)s_src[j + 3] * HID);
            float4 v0 = r0[tid], v1 = r1[tid], v2 = r2[tid], v3 = r3[tid];
            acc.x = fmaf(w0, v0.x, acc.x); acc.y = fmaf(w0, v0.y, acc.y);
            acc.z = fmaf(w0, v0.z, acc.z); acc.w = fmaf(w0, v0.w, acc.w);
            acc.x = fmaf(w1, v1.x, acc.x); acc.y = fmaf(w1, v1.y, acc.y);
            acc.z = fmaf(w1, v1.z, acc.z); acc.w = fmaf(w1, v1.w, acc.w);
            acc.x = fmaf(w2, v2.x, acc.x); acc.y = fmaf(w2, v2.y, acc.y);
            acc.z = fmaf(w2, v2.z, acc.z); acc.w = fmaf(w2, v2.w, acc.w);
            acc.x = fmaf(w3, v3.x, acc.x); acc.y = fmaf(w3, v3.y, acc.y);
            acc.z = fmaf(w3, v3.z, acc.z); acc.w = fmaf(w3, v3.w, acc.w);
        }
        for (; j < deg; j++) {
            float wgt = s_w[j];
            const float4* row = (const float4*)(g_xl + (size_t)s_src[j] * HID);
            float4 v = row[tid];
            acc.x = fmaf(wgt, v.x, acc.x);
            acc.y = fmaf(wgt, v.y, acc.y);
            acc.z = fmaf(wgt, v.z, acc.z);
            acc.w = fmaf(wgt, v.w, acc.w);
        }
    } else {
        float mx = -1e30f;
        for (int j = tid; j < deg; j += 256) mx = fmaxf(mx, g_e[beg + j]);
        red[tid] = mx; __syncthreads();
        for (int o = 128; o > 0; o >>= 1) {
            if (tid < o) red[tid] = fmaxf(red[tid], red[tid + o]);
            __syncthreads();
        }
        m = red[0];
        __syncthreads();
        float sl = 0.f;
        for (int j = tid; j < deg; j += 256) sl += __expf(g_e[beg + j] - m);
        red[tid] = sl; __syncthreads();
        for (int o = 128; o > 0; o >>= 1) {
            if (tid < o) red[tid] += red[tid + o];
            __syncthreads();
        }
        ssum = red[0];
        __syncthreads();
        for (int j = 0; j < deg; j++) {
            float wgt = __expf(g_e[beg + j] - m);
            const float4* row = (const float4*)(g_xl + (size_t)g_srcs[beg + j] * HID);
            float4 v = row[tid];
            acc.x = fmaf(wgt, v.x, acc.x);
            acc.y = fmaf(wgt, v.y, acc.y);
            acc.z = fmaf(wgt, v.z, acc.z);
            acc.w = fmaf(wgt, v.w, acc.w);
        }
    }

    float inv = 1.f / ssum;
    float4 cb = ((const float4*)conv_b)[tid];
    float4 o;
    o.x = fmaxf(fmaf(acc.x, inv, cb.x), 0.f);
    o.y = fmaxf(fmaf(acc.y, inv, cb.y), 0.f);
    o.z = fmaxf(fmaf(acc.z, inv, cb.z), 0.f);
    o.w = fmaxf(fmaf(acc.w, inv, cb.w), 0.f);

    size_t base = (size_t)node * HID + tid * 4;
    __half2* hp = (__half2*)(g_hh + base);
    hp[0] = __floats2half2_rn(o.x, o.y);
    hp[1] = __floats2half2_rn(o.z, o.w);
}

// ============================================================================
// launch
// ============================================================================
extern "C" void kernel_launch(void* const* d_in, const int* in_sizes, int n_in,
                              void* d_out, int out_size)
{
    const float* x   = (const float*)d_in[0];
    const int*   ei  = (const int*)d_in[1];
    const float* Wl  = (const float*)d_in[2];
    const float* bl  = (const float*)d_in[3];
    const float* Wr  = (const float*)d_in[4];
    const float* br  = (const float*)d_in[5];
    const float* att = (const float*)d_in[6];
    const float* cb  = (const float*)d_in[7];
    const float* W1  = (const float*)d_in[8];
    const float* b1  = (const float*)d_in[9];
    const float* W2  = (const float*)d_in[10];
    const float* b2  = (const float*)d_in[11];
    const float* Wc  = (const float*)d_in[12];
    const float* bc  = (const float*)d_in[13];

    const int n = in_sizes[0] / 512;
    const int E = in_sizes[1] / 2;
    const int total = E + n;
    const int* srcA = ei;
    const int* dstA = ei + E;

    float *xl, *xr;
    __half *xh, *hh, *Wlrt_h, *Wlrt_l, *W1t_h, *W1t_l;
    __nv_bfloat16 *h1h, *h1l, *h2h, *h2l, *W2t_h, *W2t_l, *Wct_h, *Wct_l;
    cudaGetSymbolAddress((void**)&xl,  g_xl);
    cudaGetSymbolAddress((void**)&xr,  g_xr);
    cudaGetSymbolAddress((void**)&xh,  g_xh);
    cudaGetSymbolAddress((void**)&hh,  g_hh);
    cudaGetSymbolAddress((void**)&h1h, g_h1h);
    cudaGetSymbolAddress((void**)&h1l, g_h1l);
    cudaGetSymbolAddress((void**)&h2h, g_h2h);
    cudaGetSymbolAddress((void**)&h2l, g_h2l);
    cudaGetSymbolAddress((void**)&Wlrt_h, g_Wlrt_h);
    cudaGetSymbolAddress((void**)&Wlrt_l, g_Wlrt_l);
    cudaGetSymbolAddress((void**)&W1t_h, g_W1t_h);
    cudaGetSymbolAddress((void**)&W1t_l, g_W1t_l);
    cudaGetSymbolAddress((void**)&W2t_h, g_W2t_h);
    cudaGetSymbolAddress((void**)&W2t_l, g_W2t_l);
    cudaGetSymbolAddress((void**)&Wct_h, g_Wct_h);
    cudaGetSymbolAddress((void**)&Wct_l, g_Wct_l);
    float* out = (float*)d_out;

    cudaFuncSetAttribute(gemm_mma_h<false, true, false, true>,
                         cudaFuncAttributeMaxDynamicSharedMemorySize, GSMEM_H);
    cudaFuncSetAttribute(gemm_mma_h<true, false, true, false>,
                         cudaFuncAttributeMaxDynamicSharedMemorySize, GSMEM_H);
    cudaFuncSetAttribute(gemm_mma<true, false, true, false>,
                         cudaFuncAttributeMaxDynamicSharedMemorySize, GSMEM);
    cudaFuncSetAttribute(gemm_mma<false, true, false, false>,
                         cudaFuncAttributeMaxDynamicSharedMemorySize, GSMEM);

    // conversions (fp16 x + one batched prep launch)
    int n4 = n * 512 / 4;
    split_x_kernel<<<(n4 + 255) / 256, 256>>>((const float4*)x, (__half2*)xh, n4);
    int initBlocks = (n + 255) / 256;
    prep_kernel<<<1616 + initBlocks, 256>>>(Wl, Wr, W1, W2, Wc,
                                            Wlrt_h, Wlrt_l, W1t_h, W1t_l,
                                            W2t_h, W2t_l, Wct_h, Wct_l, n);

    // combined xl|xr transform: fp16 2-term, dual fp32 outputs
    dim3 gx(2048 / 128, (n + 127) / 128);
    gemm_mma_h<false, true, false, true><<<gx, 256, GSMEM_H>>>(
        xh, Wlrt_h, Wlrt_l, bl, br, xl, xr, nullptr, nullptr, n, 2048, 512);

    count_kernel<<<(E + 255) / 256, 256>>>(dstA, E);
    scan_kernel<<<1, 1024>>>(n);
    fill_kernel<<<(total + 255) / 256, 256>>>(srcA, dstA, E, total);

    edge_e_kernel<<<(total + 7) / 8, 256>>>(att, total);
    aggregate_kernel<<<n, 256>>>(cb);

    // MLP head: W1 fp16 2-term; W2/Wc bf16 3-term
    dim3 g1(512 / 128, (n + 127) / 128);
    gemm_mma_h<true, false, true, false><<<g1, 256, GSMEM_H>>>(
        hh, W1t_h, W1t_l, b1, nullptr, nullptr, nullptr, h1h, h1l, n, 512, 1024);
    dim3 g2(1, (n + 127) / 128);
    gemm_mma<true, false, true, false><<<g2, 256, GSMEM>>>(
        h1h, h1l, W2t_h, W2t_l, b2, nullptr, nullptr, nullptr, h2h, h2l, n, 128, 512);
    dim3 g3(1, (n + 127) / 128);
    gemm_mma<false, true, false, false><<<g3, 256, GSMEM>>>(
        h2h, h2l, Wct_h, Wct_l, bc, nullptr, out, nullptr, nullptr, nullptr, n, 100, 128);
}